// round 10
// baseline (speedup 1.0000x reference)
#include <cuda_runtime.h>
#include <math.h>

// Problem dims (fixed by the dataset)
#define B 1024
#define S 64
#define E 256
#define H 512
#define V 128
#define C 32

#define HPAIR 256          // h-pairs
#define THR   1024

// buckets: NB4 CTAs (longest rows, 608..1023), NB8 CTAs (rows 0..607 desc)
#define N_CTA4  104
#define N_CTA8  76
#define RNN_GRID (N_CTA4 + N_CTA8)   // 180

// ---- smem layouts (bytes) ----
// NB4 path
#define SM4_HD    0                 // ull[256*4]      8192
#define SM4_PB    8192              // ull[256*34]     69632
#define SM4_HF    77824             // ull[256*4]      8192
#define SM4_HLIN  86016             // float[4*512]    8192
#define SM4_RED   94208             // float[4*32*8]   4096
#define SM4_INTS  98304             // orig[4],slen[4],xi[4]
// NB8 path
#define SM8_HT2   0                 // ull[512*4]      16384
#define SM8_PB    16384             // ull[256*34]     69632
#define SM8_HF    86016             // float[512*8]    16384
#define SM8_HLIN  102400            // float[8*512]    16384
#define SM8_RED   118784            // float[8*32*4]   4096
#define SM8_INTS  122880            // 96
#define RNN_SMEM  122976

// setup kernel block ranges
#define SETUP_TRANS_BLKS 2112       // 2112*256 = 540672 = 2*H*H + C*H exactly
#define SETUP_P_BLKS     128
#define SETUP_SORT_BLKS  4
#define SETUP_GRID (SETUP_TRANS_BLKS + SETUP_P_BLKS + SETUP_SORT_BLKS)

// Scratch (no allocations allowed -> __device__ globals)
__device__ float  g_P[V * H];                   // emb @ W_ih^T + b_ih + b_hh
__device__ float4 g_Wp[(H / 2) * (H / 2)];      // paired W_hh^T (1 MB)
__device__ float4 g_W1p[(H / 2) * (H / 2)];     // paired W1^T   (1 MB)
__device__ float  g_W2T[H * C];                 // W2^T [k][c]
__device__ int    g_sidx[B];
__device__ int    g_slen[B];

// ---------------------------------------------------------------------------
// f32x2 helpers
// ---------------------------------------------------------------------------
typedef unsigned long long ull;
__device__ __forceinline__ ull pk2(float x, float y) {
    ull r; asm("mov.b64 %0, {%1, %2};" : "=l"(r) : "f"(x), "f"(y)); return r;
}
__device__ __forceinline__ void upk2(ull v, float& x, float& y) {
    asm("mov.b64 {%0, %1}, %2;" : "=f"(x), "=f"(y) : "l"(v));
}
__device__ __forceinline__ void fma2(ull& d, ull a, ull b) {
    asm("fma.rn.f32x2 %0, %1, %2, %3;" : "=l"(d) : "l"(a), "l"(b), "l"(d));
}
__device__ __forceinline__ void add2(ull& d, ull a, ull b) {
    asm("add.rn.f32x2 %0, %1, %2;" : "=l"(d) : "l"(a), "l"(b));
}

// ---------------------------------------------------------------------------
// Fused setup kernel: transpose (W_hh/W1 paired, W2^T) + P table + length sort.
// All parts independent; one launch, blocks run concurrently.
// ---------------------------------------------------------------------------
__global__ void __launch_bounds__(256) setup_kernel(
        const int*   __restrict__ lens,
        const float* __restrict__ emb,
        const float* __restrict__ W_ih,
        const float* __restrict__ b_ih,
        const float* __restrict__ b_hh,
        const float* __restrict__ W_hh,
        const float* __restrict__ W1,
        const float* __restrict__ W2) {
    const int bid = blockIdx.x;
    const int tid = threadIdx.x;

    if (bid < SETUP_TRANS_BLKS) {
        int idx = bid * 256 + tid;
        if (idx < H * H) {
            int h = idx >> 9, k = idx & (H - 1);
            int kp = k >> 1, hp = h >> 1;
            reinterpret_cast<float*>(g_Wp)[(kp * HPAIR + hp) * 4 + (k & 1) * 2 + (h & 1)]
                = W_hh[idx];
        } else if (idx < 2 * H * H) {
            int j = idx - H * H;
            int h = j >> 9, k = j & (H - 1);
            int kp = k >> 1, hp = h >> 1;
            reinterpret_cast<float*>(g_W1p)[(kp * HPAIR + hp) * 4 + (k & 1) * 2 + (h & 1)]
                = W1[j];
        } else {
            int j = idx - 2 * H * H;
            int c = j >> 9, k = j & (H - 1);
            g_W2T[k * C + c] = W2[j];
        }
    } else if (bid < SETUP_TRANS_BLKS + SETUP_P_BLKS) {
        // P[v][h] = sum_e emb[v,e]*W_ih[h,e] + b_ih[h] + b_hh[h]; 256 thr, 2 h each
        __shared__ float es[E];
        const int v = bid - SETUP_TRANS_BLKS;
        es[tid] = emb[v * E + tid];
        __syncthreads();
        const float4* e4 = reinterpret_cast<const float4*>(es);
#pragma unroll
        for (int r = 0; r < 2; r++) {
            const int h = tid + r * 256;
            float acc = b_ih[h] + b_hh[h];
            const float4* w = reinterpret_cast<const float4*>(W_ih + h * E);
#pragma unroll 8
            for (int i = 0; i < E / 4; i++) {
                float4 a = e4[i], b = w[i];
                acc += a.x * b.x + a.y * b.y + a.z * b.z + a.w * b.w;
            }
            g_P[v * H + h] = acc;
        }
    } else {
        // stable rank sort by length
        const int i  = (bid - SETUP_TRANS_BLKS - SETUP_P_BLKS) * 256 + tid;
        const int my = __ldg(lens + i);
        int rank = 0;
#pragma unroll 8
        for (int j = 0; j < B; j++) {
            int lj = __ldg(lens + j);
            rank += (lj < my) || (lj == my && j < i);
        }
        g_sidx[rank] = i;
        g_slen[rank] = my;
    }
}

// ---------------------------------------------------------------------------
// NB4 GEMM pass for one k-group: 32 kp, double-buffered W prefetch.
// hd[kpi][b] = float2(h[2kpi], h[2kpi+1]); W from paired layout (16B/kp/hp).
// a0[b] accumulates (h-out 2hp0, 2hp0+1) f32x2; a1 likewise for hp1.
// ---------------------------------------------------------------------------
__device__ __forceinline__ void gemm4(const ulonglong2* __restrict__ Wb,
                                      const ull* __restrict__ hd, int kb,
                                      int hp0, int hp1,
                                      ull* __restrict__ a0, ull* __restrict__ a1) {
    ulonglong2 wa0 = __ldg(Wb + (kb + 0) * HPAIR + hp0);
    ulonglong2 wa1 = __ldg(Wb + (kb + 0) * HPAIR + hp1);
    ulonglong2 wc0 = __ldg(Wb + (kb + 1) * HPAIR + hp0);
    ulonglong2 wc1 = __ldg(Wb + (kb + 1) * HPAIR + hp1);
#pragma unroll 4
    for (int c = 0; c < 32; c += 2) {
        const int n0 = (c + 2) & 31;
        const int n1 = (c + 3) & 31;
        ulonglong2 wb0 = __ldg(Wb + (kb + n0) * HPAIR + hp0);
        ulonglong2 wb1 = __ldg(Wb + (kb + n0) * HPAIR + hp1);
        {
            const float4* hk =
                reinterpret_cast<const float4*>(hd + (unsigned)(kb + c) * 4);
            float4 qA = hk[0];
            float4 qB = hk[1];
            {
                ull d0 = pk2(qA.x, qA.x), d1 = pk2(qA.z, qA.z);
                ull d2 = pk2(qB.x, qB.x), d3 = pk2(qB.z, qB.z);
                fma2(a0[0], wa0.x, d0); fma2(a0[1], wa0.x, d1);
                fma2(a0[2], wa0.x, d2); fma2(a0[3], wa0.x, d3);
                fma2(a1[0], wa1.x, d0); fma2(a1[1], wa1.x, d1);
                fma2(a1[2], wa1.x, d2); fma2(a1[3], wa1.x, d3);
            }
            {
                ull d0 = pk2(qA.y, qA.y), d1 = pk2(qA.w, qA.w);
                ull d2 = pk2(qB.y, qB.y), d3 = pk2(qB.w, qB.w);
                fma2(a0[0], wa0.y, d0); fma2(a0[1], wa0.y, d1);
                fma2(a0[2], wa0.y, d2); fma2(a0[3], wa0.y, d3);
                fma2(a1[0], wa1.y, d0); fma2(a1[1], wa1.y, d1);
                fma2(a1[2], wa1.y, d2); fma2(a1[3], wa1.y, d3);
            }
        }
        ulonglong2 wd0 = __ldg(Wb + (kb + n1) * HPAIR + hp0);
        ulonglong2 wd1 = __ldg(Wb + (kb + n1) * HPAIR + hp1);
        {
            const float4* hk =
                reinterpret_cast<const float4*>(hd + (unsigned)(kb + c + 1) * 4);
            float4 qA = hk[0];
            float4 qB = hk[1];
            {
                ull d0 = pk2(qA.x, qA.x), d1 = pk2(qA.z, qA.z);
                ull d2 = pk2(qB.x, qB.x), d3 = pk2(qB.z, qB.z);
                fma2(a0[0], wc0.x, d0); fma2(a0[1], wc0.x, d1);
                fma2(a0[2], wc0.x, d2); fma2(a0[3], wc0.x, d3);
                fma2(a1[0], wc1.x, d0); fma2(a1[1], wc1.x, d1);
                fma2(a1[2], wc1.x, d2); fma2(a1[3], wc1.x, d3);
            }
            {
                ull d0 = pk2(qA.y, qA.y), d1 = pk2(qA.w, qA.w);
                ull d2 = pk2(qB.y, qB.y), d3 = pk2(qB.w, qB.w);
                fma2(a0[0], wc0.y, d0); fma2(a0[1], wc0.y, d1);
                fma2(a0[2], wc0.y, d2); fma2(a0[3], wc0.y, d3);
                fma2(a1[0], wc1.y, d0); fma2(a1[1], wc1.y, d1);
                fma2(a1[2], wc1.y, d2); fma2(a1[3], wc1.y, d3);
            }
        }
        wa0 = wb0; wa1 = wb1; wc0 = wd0; wc1 = wd1;
    }
}

// ---------------------------------------------------------------------------
// NB=4 body: RNN time loop + fused MLP head.  8-way k-split (2 hp / thread).
// ---------------------------------------------------------------------------
__device__ __forceinline__ void rnn_body4(const int* __restrict__ x_in,
                                          const float* __restrict__ b1,
                                          const float* __restrict__ b2,
                                          float* __restrict__ out,
                                          int rowbase, char* smem) {
    ull*   hd   = reinterpret_cast<ull*>(smem + SM4_HD);
    ull*   pB   = reinterpret_cast<ull*>(smem + SM4_PB);
    ull*   hf   = reinterpret_cast<ull*>(smem + SM4_HF);
    float* hlin = reinterpret_cast<float*>(smem + SM4_HLIN);
    float* red  = reinterpret_cast<float*>(smem + SM4_RED);
    int* ints = reinterpret_cast<int*>(smem + SM4_INTS);
    int* orig = ints;
    int* slen = ints + 4;
    int* xi   = ints + 8;

    const int tid = threadIdx.x;
    const int grp = tid >> 7;              // 0..7
    const int u   = tid & 127;
    const int hp0 = u;
    const int hp1 = u + 128;

    const int ehp = tid >> 2;              // 0..255
    const int eb  = tid & 3;

    if (tid < 4) {
        orig[tid] = g_sidx[rowbase + tid];
        slen[tid] = g_slen[rowbase + tid];
    }
    for (int i = tid; i < 256 * 4; i += THR) hd[i] = 0ull;
    __syncthreads();

    int tmax = 0;
#pragma unroll
    for (int b = 0; b < 4; b++) tmax = max(tmax, slen[b]);

    const ulonglong2* Wb  = reinterpret_cast<const ulonglong2*>(g_Wp);
    const ulonglong2* W1b = reinterpret_cast<const ulonglong2*>(g_W1p);
    const int kb = grp * 32;

    ull*       wr0 = pB + hp0 * 34 + grp * 4;
    ull*       wr1 = pB + hp1 * 34 + grp * 4;
    const ull* rd  = pB + ehp * 34 + eb;

    for (int t = 0; t < tmax; t++) {
        if (tid < 4) xi[tid] = x_in[orig[tid] * S + t];
        __syncthreads();    // (1) xi ready; hd from previous epilogue visible

        float2 pf = __ldg(reinterpret_cast<const float2*>(g_P + xi[eb] * H) + ehp);

        ull a0[4], a1[4];
#pragma unroll
        for (int b = 0; b < 4; b++) { a0[b] = 0ull; a1[b] = 0ull; }

        gemm4(Wb, hd, kb, hp0, hp1, a0, a1);

        *reinterpret_cast<ulonglong2*>(wr0)     = make_ulonglong2(a0[0], a0[1]);
        *reinterpret_cast<ulonglong2*>(wr0 + 2) = make_ulonglong2(a0[2], a0[3]);
        *reinterpret_cast<ulonglong2*>(wr1)     = make_ulonglong2(a1[0], a1[1]);
        *reinterpret_cast<ulonglong2*>(wr1 + 2) = make_ulonglong2(a1[2], a1[3]);
        __syncthreads();    // (2) partials visible; all hd reads complete

        ull s = rd[0];
#pragma unroll
        for (int g = 1; g < 8; g++) {
            ull v = rd[g * 4];
            add2(s, s, v);
        }
        add2(s, s, pk2(pf.x, pf.y));

        float x0, x1;
        upk2(s, x0, x1);
        const float v0 = tanhf(x0);
        const float v1 = tanhf(x1);

        hd[ehp * 4 + eb] = pk2(v0, v1);
        if (t == slen[eb] - 1) hf[ehp * 4 + eb] = pk2(v0, v1);
    }
    __syncthreads();        // hf complete; last step's pB reads done

    // ---- fused MLP: hidden = relu(W1 @ hf + b1) ----
    {
        ull a0[4], a1[4];
#pragma unroll
        for (int b = 0; b < 4; b++) { a0[b] = 0ull; a1[b] = 0ull; }

        gemm4(W1b, hf, kb, hp0, hp1, a0, a1);

        *reinterpret_cast<ulonglong2*>(wr0)     = make_ulonglong2(a0[0], a0[1]);
        *reinterpret_cast<ulonglong2*>(wr0 + 2) = make_ulonglong2(a0[2], a0[3]);
        *reinterpret_cast<ulonglong2*>(wr1)     = make_ulonglong2(a1[0], a1[1]);
        *reinterpret_cast<ulonglong2*>(wr1 + 2) = make_ulonglong2(a1[2], a1[3]);
        __syncthreads();

        ull s = rd[0];
#pragma unroll
        for (int g = 1; g < 8; g++) {
            ull v = rd[g * 4];
            add2(s, s, v);
        }
        float2 bv = __ldg(reinterpret_cast<const float2*>(b1) + ehp);
        float x0, x1;
        upk2(s, x0, x1);
        *reinterpret_cast<float2*>(hlin + eb * H + 2 * ehp) =
            make_float2(fmaxf(x0 + bv.x, 0.f), fmaxf(x1 + bv.y, 0.f));
    }
    __syncthreads();

    // ---- logits: 4 rows x 32 classes, 8-way k-split ----
    {
        const int lb = tid >> 8;           // 0..3
        const int lc = (tid >> 3) & 31;
        const int lk = tid & 7;
        float acc = 0.f;
        const float* hb = hlin + lb * H + lk * 64;
        const float* w2 = g_W2T + (lk * 64) * C + lc;
#pragma unroll 8
        for (int j = 0; j < 64; j++) acc += hb[j] * __ldg(w2 + j * C);
        red[(tid >> 3) * 8 + lk] = acc;
    }
    __syncthreads();
    if (tid < 128) {
        const int b = tid >> 5, c = tid & 31;
        float acc = __ldg(b2 + c);
#pragma unroll
        for (int g = 0; g < 8; g++) acc += red[tid * 8 + g];
        out[orig[b] * C + c] = acc;
    }
}

// ---------------------------------------------------------------------------
// NB8 packed-batch inner compute: 4 kp (8 k), weights in regs.
// ---------------------------------------------------------------------------
__device__ __forceinline__ void comp4T8(const ull* __restrict__ hT2, int k0,
                                        const ulonglong2 w[4],
                                        ull* __restrict__ a0, ull* __restrict__ a1) {
#pragma unroll
    for (int j = 0; j < 4; j++) {
#pragma unroll
        for (int kk = 0; kk < 2; kk++) {
            const int k = k0 + 2 * j + kk;
            float wl, wh;
            upk2(kk ? w[j].y : w[j].x, wl, wh);
            ull s0 = pk2(wl, wl), s1 = pk2(wh, wh);
            const ulonglong2* hk =
                reinterpret_cast<const ulonglong2*>(hT2 + (unsigned)k * 4);
#pragma unroll
            for (int p = 0; p < 2; p++) {
                ulonglong2 hv = hk[p];
                fma2(a0[2 * p], hv.x, s0); fma2(a0[2 * p + 1], hv.y, s0);
                fma2(a1[2 * p], hv.x, s1); fma2(a1[2 * p + 1], hv.y, s1);
            }
        }
    }
}

__device__ __forceinline__ void gemm8(const ulonglong2* __restrict__ Wp,
                                      const ull* __restrict__ hT2, int kbase,
                                      ull* __restrict__ a0, ull* __restrict__ a1) {
    ulonglong2 wA[4], wB[4];
#pragma unroll
    for (int j = 0; j < 4; j++) wA[j] = __ldg(Wp + j * HPAIR);
#pragma unroll 1
    for (int c = 0; c < 64; c += 8) {
#pragma unroll
        for (int j = 0; j < 4; j++) wB[j] = __ldg(Wp + (c + 4 + j) * HPAIR);
        comp4T8(hT2, kbase + 2 * c, wA, a0, a1);
        const int nc = (c + 8) & 63;
#pragma unroll
        for (int j = 0; j < 4; j++) wA[j] = __ldg(Wp + (nc + j) * HPAIR);
        comp4T8(hT2, kbase + 2 * (c + 4), wB, a0, a1);
    }
}

// ---------------------------------------------------------------------------
// NB=8 body: RNN time loop + fused MLP head. 4-way k-split.
// ---------------------------------------------------------------------------
__device__ __forceinline__ void rnn_body8(const int* __restrict__ x_in,
                                          const float* __restrict__ b1,
                                          const float* __restrict__ b2,
                                          float* __restrict__ out,
                                          int rowbase, char* smem) {
    constexpr int NB = 8;
    constexpr int PBS = 34;
    ull*   hT2  = reinterpret_cast<ull*>(smem + SM8_HT2);
    ull*   pB   = reinterpret_cast<ull*>(smem + SM8_PB);
    float* hff  = reinterpret_cast<float*>(smem + SM8_HF);    // [512][8]
    float* hlin = reinterpret_cast<float*>(smem + SM8_HLIN);  // [8][512]
    float* red  = reinterpret_cast<float*>(smem + SM8_RED);
    int* ints = reinterpret_cast<int*>(smem + SM8_INTS);
    int* orig = ints;
    int* slen = ints + NB;
    int* xi   = ints + 2 * NB;

    const int tid = threadIdx.x;
    const int grp = tid >> 8;
    const int hp  = tid & (HPAIR - 1);

    const int eh   = tid >> 1;
    const int eq   = tid & 1;
    const int ehp  = eh >> 1;
    const int epar = eh & 1;

    if (tid < NB) {
        orig[tid] = g_sidx[rowbase + tid];
        slen[tid] = g_slen[rowbase + tid];
    }
    for (int i = tid; i < 512 * 4; i += THR) hT2[i] = 0ull;
    __syncthreads();

    int tmax = 0;
#pragma unroll
    for (int b = 0; b < NB; b++) tmax = max(tmax, slen[b]);

    const ulonglong2* Wp =
        reinterpret_cast<const ulonglong2*>(g_Wp) + (grp * 64) * HPAIR + hp;
    const ulonglong2* W1p =
        reinterpret_cast<const ulonglong2*>(g_W1p) + (grp * 64) * HPAIR + hp;
    const int kbase = grp * 128;

    ull*       myPB = pB + hp * PBS + grp * NB;
    const ull* ePB  = pB + ehp * PBS + epar * 4 + eq * 2;

    for (int t = 0; t < tmax; t++) {
        if (tid < NB) xi[tid] = x_in[orig[tid] * S + t];
        __syncthreads();

        float pf[4];
#pragma unroll
        for (int i = 0; i < 4; i++)
            pf[i] = __ldg(g_P + xi[eq * 4 + i] * H + eh);

        ull a0[4], a1[4];
#pragma unroll
        for (int p = 0; p < 4; p++) { a0[p] = 0ull; a1[p] = 0ull; }

        gemm8(Wp, hT2, kbase, a0, a1);

#pragma unroll
        for (int p = 0; p < 4; p += 2)
            *reinterpret_cast<ulonglong2*>(myPB + p) =
                make_ulonglong2(a0[p], a0[p + 1]);
#pragma unroll
        for (int p = 0; p < 4; p += 2)
            *reinterpret_cast<ulonglong2*>(myPB + 4 + p) =
                make_ulonglong2(a1[p], a1[p + 1]);
        __syncthreads();

        ull s[2];
#pragma unroll
        for (int q = 0; q < 2; q++) s[q] = ePB[q];
#pragma unroll
        for (int g = 1; g < 4; g++) {
#pragma unroll
            for (int q = 0; q < 2; q++) {
                ull v = ePB[g * NB + q];
                add2(s[q], s[q], v);
            }
        }
#pragma unroll
        for (int q = 0; q < 2; q++)
            add2(s[q], s[q], pk2(pf[2 * q], pf[2 * q + 1]));

        float v[4];
#pragma unroll
        for (int q = 0; q < 2; q++) {
            float x, y;
            upk2(s[q], x, y);
            v[2 * q]     = tanhf(x);
            v[2 * q + 1] = tanhf(y);
        }
#pragma unroll
        for (int q = 0; q < 2; q++)
            hT2[eh * 4 + eq * 2 + q] = pk2(v[2 * q], v[2 * q + 1]);

#pragma unroll
        for (int i = 0; i < 4; i++) {
            const int b = eq * 4 + i;
            if (t == slen[b] - 1) hff[eh * NB + b] = v[i];
        }
    }
    __syncthreads();        // hff complete; last step's reads done

    // repack hff into hT2 paired layout for the MLP GEMM
    {
        const float* src = hff + eh * NB + eq * 4;
        hT2[eh * 4 + eq * 2 + 0] = pk2(src[0], src[1]);
        hT2[eh * 4 + eq * 2 + 1] = pk2(src[2], src[3]);
    }
    __syncthreads();

    // ---- fused MLP: hidden = relu(W1 @ hfinal + b1) ----
    {
        ull a0[4], a1[4];
#pragma unroll
        for (int p = 0; p < 4; p++) { a0[p] = 0ull; a1[p] = 0ull; }

        gemm8(W1p, hT2, kbase, a0, a1);

#pragma unroll
        for (int p = 0; p < 4; p += 2)
            *reinterpret_cast<ulonglong2*>(myPB + p) =
                make_ulonglong2(a0[p], a0[p + 1]);
#pragma unroll
        for (int p = 0; p < 4; p += 2)
            *reinterpret_cast<ulonglong2*>(myPB + 4 + p) =
                make_ulonglong2(a1[p], a1[p + 1]);
        __syncthreads();

        ull s[2];
#pragma unroll
        for (int q = 0; q < 2; q++) s[q] = ePB[q];
#pragma unroll
        for (int g = 1; g < 4; g++) {
#pragma unroll
            for (int q = 0; q < 2; q++) {
                ull v = ePB[g * NB + q];
                add2(s[q], s[q], v);
            }
        }
        const float bv = __ldg(b1 + eh);
#pragma unroll
        for (int q = 0; q < 2; q++) {
            float x, y;
            upk2(s[q], x, y);
            hlin[(eq * 4 + 2 * q + 0) * H + eh] = fmaxf(x + bv, 0.f);
            hlin[(eq * 4 + 2 * q + 1) * H + eh] = fmaxf(y + bv, 0.f);
        }
    }
    __syncthreads();

    // ---- logits: 8 rows x 32 classes, 4-way k-split ----
    {
        const int lb = tid >> 7;           // 0..7
        const int lc = (tid >> 2) & 31;
        const int lk = tid & 3;
        float acc = 0.f;
        const float* hb = hlin + lb * H + lk * 128;
        const float* w2 = g_W2T + (lk * 128) * C + lc;
#pragma unroll 8
        for (int j = 0; j < 128; j++) acc += hb[j] * __ldg(w2 + j * C);
        red[(tid >> 2) * 4 + lk] = acc;
    }
    __syncthreads();
    if (tid < 256) {
        const int b = tid >> 5, c = tid & 31;
        float acc = __ldg(b2 + c);
#pragma unroll
        for (int g = 0; g < 4; g++) acc += red[tid * 4 + g];
        out[orig[b] * C + c] = acc;
    }
}

// ---------------------------------------------------------------------------
// Bucketed persistent RNN + fused MLP.
//   bid 0..103   : NB=4, rows 608 + 4*bid (longest 416 rows)
//   bid 104..179 : NB=8, rows 600 - 8*(bid-104) (descending; shortest last)
// ---------------------------------------------------------------------------
__global__ void __launch_bounds__(THR, 1) rnn_kernel(const int* __restrict__ x_in,
                                                     const float* __restrict__ b1,
                                                     const float* __restrict__ b2,
                                                     float* __restrict__ out) {
    extern __shared__ char smem[];
    const int bid = blockIdx.x;
    if (bid < N_CTA4) {
        rnn_body4(x_in, b1, b2, out, 608 + 4 * bid, smem);
    } else {
        rnn_body8(x_in, b1, b2, out, 600 - 8 * (bid - N_CTA4), smem);
    }
}

// ---------------------------------------------------------------------------
extern "C" void kernel_launch(void* const* d_in, const int* in_sizes, int n_in,
                              void* d_out, int out_size) {
    const int*   x_in   = (const int*)  d_in[0];
    const int*   x_lens = (const int*)  d_in[1];
    const float* emb    = (const float*)d_in[2];
    const float* W_ih   = (const float*)d_in[3];
    const float* b_ih   = (const float*)d_in[4];
    const float* W_hh   = (const float*)d_in[5];
    const float* b_hh   = (const float*)d_in[6];
    const float* W1w    = (const float*)d_in[7];
    const float* b1     = (const float*)d_in[8];
    const float* W2w    = (const float*)d_in[9];
    const float* b2     = (const float*)d_in[10];
    float* out = (float*)d_out;

    cudaFuncSetAttribute(rnn_kernel,
                         cudaFuncAttributeMaxDynamicSharedMemorySize, RNN_SMEM);

    setup_kernel<<<SETUP_GRID, 256>>>(x_lens, emb, W_ih, b_ih, b_hh,
                                      W_hh, W1w, W2w);
    rnn_kernel<<<RNN_GRID, THR, RNN_SMEM>>>(x_in, b1, b2, out);
}

// round 11
// speedup vs baseline: 1.0683x; 1.0683x over previous
#include <cuda_runtime.h>
#include <math.h>

// Problem dims (fixed by the dataset)
#define B 1024
#define S 64
#define E 256
#define H 512
#define V 128
#define C 32

#define BT    8
#define HPAIR 256          // h-pairs
#define THR   1024

// buckets: NB4 CTAs (longest rows, 608..1023), NB8 CTAs (rows 0..607 desc)
#define N_CTA4  104
#define N_CTA8  76
#define RNN_GRID (N_CTA4 + N_CTA8)   // 180

// dynamic smem (worst case = NB8 path): 16384 (state) + 69632 (partials) + ints
#define RNN_SMEM (16384 + 69632 + 96)

// mlp smem layout
#define MLP_HT2  0
#define MLP_PB   16384
#define MLP_HLIN 86016
#define MLP_RED  102400
#define MLP_SMEM (102400 + 5120)

// setup kernel block ranges
#define SETUP_TRANS_BLKS 2112       // 2112*256 = 540672 = 2*H*H + C*H exactly
#define SETUP_P_BLKS     128
#define SETUP_SORT_BLKS  4
#define SETUP_GRID (SETUP_TRANS_BLKS + SETUP_P_BLKS + SETUP_SORT_BLKS)

// Scratch (no allocations allowed -> __device__ globals)
__device__ float  g_P[V * H];                   // emb @ W_ih^T + b_ih + b_hh
__device__ float4 g_Wp[(H / 2) * (H / 2)];      // paired W_hh^T (1 MB)
__device__ float4 g_W1p[(H / 2) * (H / 2)];     // paired W1^T   (1 MB)
__device__ float  g_W2T[H * C];                 // W2^T [k][c]
__device__ float  g_last[B * H];                // h at t=len-1, original order
__device__ int    g_sidx[B];
__device__ int    g_slen[B];

// ---------------------------------------------------------------------------
// f32x2 helpers
// ---------------------------------------------------------------------------
typedef unsigned long long ull;
__device__ __forceinline__ ull pk2(float x, float y) {
    ull r; asm("mov.b64 %0, {%1, %2};" : "=l"(r) : "f"(x), "f"(y)); return r;
}
__device__ __forceinline__ void upk2(ull v, float& x, float& y) {
    asm("mov.b64 {%0, %1}, %2;" : "=f"(x), "=f"(y) : "l"(v));
}
__device__ __forceinline__ void fma2(ull& d, ull a, ull b) {
    asm("fma.rn.f32x2 %0, %1, %2, %3;" : "=l"(d) : "l"(a), "l"(b), "l"(d));
}
__device__ __forceinline__ void add2(ull& d, ull a, ull b) {
    asm("add.rn.f32x2 %0, %1, %2;" : "=l"(d) : "l"(a), "l"(b));
}

// ---------------------------------------------------------------------------
// Fused setup kernel: transpose (W_hh/W1 paired, W2^T) + P table + length sort.
// All parts independent; one launch, blocks run concurrently.
// ---------------------------------------------------------------------------
__global__ void __launch_bounds__(256) setup_kernel(
        const int*   __restrict__ lens,
        const float* __restrict__ emb,
        const float* __restrict__ W_ih,
        const float* __restrict__ b_ih,
        const float* __restrict__ b_hh,
        const float* __restrict__ W_hh,
        const float* __restrict__ W1,
        const float* __restrict__ W2) {
    const int bid = blockIdx.x;
    const int tid = threadIdx.x;

    if (bid < SETUP_TRANS_BLKS) {
        int idx = bid * 256 + tid;
        if (idx < H * H) {
            int h = idx >> 9, k = idx & (H - 1);
            int kp = k >> 1, hp = h >> 1;
            reinterpret_cast<float*>(g_Wp)[(kp * HPAIR + hp) * 4 + (k & 1) * 2 + (h & 1)]
                = W_hh[idx];
        } else if (idx < 2 * H * H) {
            int j = idx - H * H;
            int h = j >> 9, k = j & (H - 1);
            int kp = k >> 1, hp = h >> 1;
            reinterpret_cast<float*>(g_W1p)[(kp * HPAIR + hp) * 4 + (k & 1) * 2 + (h & 1)]
                = W1[j];
        } else {
            int j = idx - 2 * H * H;
            int c = j >> 9, k = j & (H - 1);
            g_W2T[k * C + c] = W2[j];
        }
    } else if (bid < SETUP_TRANS_BLKS + SETUP_P_BLKS) {
        // P[v][h] = sum_e emb[v,e]*W_ih[h,e] + b_ih[h] + b_hh[h]; 256 thr, 2 h each
        __shared__ float es[E];
        const int v = bid - SETUP_TRANS_BLKS;
        es[tid] = emb[v * E + tid];
        __syncthreads();
        const float4* e4 = reinterpret_cast<const float4*>(es);
#pragma unroll
        for (int r = 0; r < 2; r++) {
            const int h = tid + r * 256;
            float acc = b_ih[h] + b_hh[h];
            const float4* w = reinterpret_cast<const float4*>(W_ih + h * E);
#pragma unroll 8
            for (int i = 0; i < E / 4; i++) {
                float4 a = e4[i], b = w[i];
                acc += a.x * b.x + a.y * b.y + a.z * b.z + a.w * b.w;
            }
            g_P[v * H + h] = acc;
        }
    } else {
        // stable rank sort by length
        const int i  = (bid - SETUP_TRANS_BLKS - SETUP_P_BLKS) * 256 + tid;
        const int my = __ldg(lens + i);
        int rank = 0;
#pragma unroll 8
        for (int j = 0; j < B; j++) {
            int lj = __ldg(lens + j);
            rank += (lj < my) || (lj == my && j < i);
        }
        g_sidx[rank] = i;
        g_slen[rank] = my;
    }
}

// ---------------------------------------------------------------------------
// Packed-batch inner compute (NB8 + mlp): 4 kp (8 k), weights in regs.
// hT2 (ull view): [k][NB/2] — pair p holds batches (2p, 2p+1).
// ---------------------------------------------------------------------------
template <int NB>
__device__ __forceinline__ void comp4T(const ull* __restrict__ hT2, int k0,
                                       const ulonglong2 w[4],
                                       ull* __restrict__ a0, ull* __restrict__ a1) {
#pragma unroll
    for (int j = 0; j < 4; j++) {
#pragma unroll
        for (int kk = 0; kk < 2; kk++) {
            const int k = k0 + 2 * j + kk;
            float wl, wh;
            upk2(kk ? w[j].y : w[j].x, wl, wh);
            ull s0 = pk2(wl, wl), s1 = pk2(wh, wh);
            const ulonglong2* hk =
                reinterpret_cast<const ulonglong2*>(hT2 + (unsigned)k * (NB / 2));
#pragma unroll
            for (int p = 0; p < NB / 4; p++) {
                ulonglong2 hv = hk[p];
                fma2(a0[2 * p], hv.x, s0); fma2(a0[2 * p + 1], hv.y, s0);
                fma2(a1[2 * p], hv.x, s1); fma2(a1[2 * p + 1], hv.y, s1);
            }
        }
    }
}

// 64-kp GEMM pass: 8-kp chunks, double-buffered W prefetch
template <int NB>
__device__ __forceinline__ void gemm_g6(const ulonglong2* __restrict__ Wp,
                                        const ull* __restrict__ hT2, int kbase,
                                        ull* __restrict__ a0, ull* __restrict__ a1) {
    ulonglong2 wA[4], wB[4];
#pragma unroll
    for (int j = 0; j < 4; j++) wA[j] = __ldg(Wp + j * HPAIR);
#pragma unroll 1
    for (int c = 0; c < 64; c += 8) {
#pragma unroll
        for (int j = 0; j < 4; j++) wB[j] = __ldg(Wp + (c + 4 + j) * HPAIR);
        comp4T<NB>(hT2, kbase + 2 * c, wA, a0, a1);
        const int nc = (c + 8) & 63;        // wrap dummy on last iter
#pragma unroll
        for (int j = 0; j < 4; j++) wA[j] = __ldg(Wp + (nc + j) * HPAIR);
        comp4T<NB>(hT2, kbase + 2 * (c + 4), wB, a0, a1);
    }
}

// ---------------------------------------------------------------------------
// NB=8 RNN body (proven round-6 version): 4-way k-split, packed-batch state.
// ---------------------------------------------------------------------------
__device__ __forceinline__ void rnn_body8(const int* __restrict__ x_in,
                                          int rowbase, char* smem) {
    constexpr int NB = 8;
    constexpr int PBS = 34;
    ull* hT2 = reinterpret_cast<ull*>(smem);                   // [512][4]
    ull* pB  = hT2 + 512 * 4;                                  // [256][34]
    int* ints = reinterpret_cast<int*>(pB + 256 * PBS);
    int* orig = ints;
    int* slen = ints + NB;
    int* xi   = ints + 2 * NB;

    const int tid = threadIdx.x;
    const int grp = tid >> 8;
    const int hp  = tid & (HPAIR - 1);

    const int eh   = tid >> 1;
    const int eq   = tid & 1;
    const int ehp  = eh >> 1;
    const int epar = eh & 1;

    if (tid < NB) {
        orig[tid] = g_sidx[rowbase + tid];
        slen[tid] = g_slen[rowbase + tid];
    }
    for (int i = tid; i < 512 * 4; i += THR) hT2[i] = 0ull;
    __syncthreads();

    int tmax = 0;
#pragma unroll
    for (int b = 0; b < NB; b++) tmax = max(tmax, slen[b]);

    const ulonglong2* Wp =
        reinterpret_cast<const ulonglong2*>(g_Wp) + (grp * 64) * HPAIR + hp;
    const int kbase = grp * 128;

    ull*       myPB = pB + hp * PBS + grp * NB;
    const ull* ePB  = pB + ehp * PBS + epar * 4 + eq * 2;

    for (int t = 0; t < tmax; t++) {
        if (tid < NB) xi[tid] = x_in[orig[tid] * S + t];
        __syncthreads();

        float pf[4];
#pragma unroll
        for (int i = 0; i < 4; i++)
            pf[i] = __ldg(g_P + xi[eq * 4 + i] * H + eh);

        ull a0[4], a1[4];
#pragma unroll
        for (int p = 0; p < 4; p++) { a0[p] = 0ull; a1[p] = 0ull; }

        gemm_g6<8>(Wp, hT2, kbase, a0, a1);

#pragma unroll
        for (int p = 0; p < 4; p += 2)
            *reinterpret_cast<ulonglong2*>(myPB + p) =
                make_ulonglong2(a0[p], a0[p + 1]);
#pragma unroll
        for (int p = 0; p < 4; p += 2)
            *reinterpret_cast<ulonglong2*>(myPB + 4 + p) =
                make_ulonglong2(a1[p], a1[p + 1]);
        __syncthreads();

        ull s[2];
#pragma unroll
        for (int q = 0; q < 2; q++) s[q] = ePB[q];
#pragma unroll
        for (int g = 1; g < 4; g++) {
#pragma unroll
            for (int q = 0; q < 2; q++) {
                ull v = ePB[g * NB + q];
                add2(s[q], s[q], v);
            }
        }
#pragma unroll
        for (int q = 0; q < 2; q++)
            add2(s[q], s[q], pk2(pf[2 * q], pf[2 * q + 1]));

        float v[4];
#pragma unroll
        for (int q = 0; q < 2; q++) {
            float x, y;
            upk2(s[q], x, y);
            v[2 * q]     = tanhf(x);
            v[2 * q + 1] = tanhf(y);
        }
#pragma unroll
        for (int q = 0; q < 2; q++)
            hT2[eh * 4 + eq * 2 + q] = pk2(v[2 * q], v[2 * q + 1]);

#pragma unroll
        for (int i = 0; i < 4; i++) {
            const int b = eq * 4 + i;
            if (t == slen[b] - 1) g_last[orig[b] * H + eh] = v[i];
        }
    }
}

// ---------------------------------------------------------------------------
// NB=4 RNN body — non-duplicated state, minimal LDS traffic.
// 8-way k-split; thread owns h-pairs hp0 = tid&127 and hp1 = hp0+128.
// State hd[kp][b] = float2(h[2kp], h[2kp+1])  (8 B per (kp,b); 8 KB total).
// ---------------------------------------------------------------------------
__device__ __forceinline__ void rnn_body4(const int* __restrict__ x_in,
                                          int rowbase, char* smem) {
    ull* hd = reinterpret_cast<ull*>(smem);                    // [256][4] float2
    ull* pB = hd + 256 * 4;                                    // [256][34]
    int* ints = reinterpret_cast<int*>(pB + 256 * 34);
    int* orig = ints;
    int* slen = ints + 4;
    int* xi   = ints + 8;

    const int tid = threadIdx.x;
    const int grp = tid >> 7;              // 0..7
    const int u   = tid & 127;
    const int hp0 = u;
    const int hp1 = u + 128;

    // epilogue role: thread = (h-pair ehp, batch eb)
    const int ehp = tid >> 2;              // 0..255
    const int eb  = tid & 3;

    if (tid < 4) {
        orig[tid] = g_sidx[rowbase + tid];
        slen[tid] = g_slen[rowbase + tid];
    }
    for (int i = tid; i < 256 * 4; i += THR) hd[i] = 0ull;
    __syncthreads();

    int tmax = 0;
#pragma unroll
    for (int b = 0; b < 4; b++) tmax = max(tmax, slen[b]);

    const ulonglong2* Wb = reinterpret_cast<const ulonglong2*>(g_Wp);
    const int kb = grp * 32;               // kp base for this group

    ull*       wr0 = pB + hp0 * 34 + grp * 4;
    ull*       wr1 = pB + hp1 * 34 + grp * 4;
    const ull* rd  = pB + ehp * 34 + eb;

    for (int t = 0; t < tmax; t++) {
        if (tid < 4) xi[tid] = x_in[orig[tid] * S + t];
        __syncthreads();    // (1) xi ready; hd from previous epilogue visible

        float2 pf = __ldg(reinterpret_cast<const float2*>(g_P + xi[eb] * H) + ehp);

        ull a0[4], a1[4];
#pragma unroll
        for (int b = 0; b < 4; b++) { a0[b] = 0ull; a1[b] = 0ull; }

        // 32 kp, 2-kp unrolled, double-buffered W prefetch
        ulonglong2 wa0 = __ldg(Wb + (kb + 0) * HPAIR + hp0);
        ulonglong2 wa1 = __ldg(Wb + (kb + 0) * HPAIR + hp1);
        ulonglong2 wc0 = __ldg(Wb + (kb + 1) * HPAIR + hp0);
        ulonglong2 wc1 = __ldg(Wb + (kb + 1) * HPAIR + hp1);
#pragma unroll 4
        for (int c = 0; c < 32; c += 2) {
            const int n0 = (c + 2) & 31;
            const int n1 = (c + 3) & 31;
            ulonglong2 wb0 = __ldg(Wb + (kb + n0) * HPAIR + hp0);
            ulonglong2 wb1 = __ldg(Wb + (kb + n0) * HPAIR + hp1);
            {
                const float4* hk =
                    reinterpret_cast<const float4*>(hd + (unsigned)(kb + c) * 4);
                float4 qA = hk[0];   // b0:(ke,ko), b1:(ke,ko)
                float4 qB = hk[1];   // b2:(ke,ko), b3:(ke,ko)
                {   // k even
                    ull d0 = pk2(qA.x, qA.x), d1 = pk2(qA.z, qA.z);
                    ull d2 = pk2(qB.x, qB.x), d3 = pk2(qB.z, qB.z);
                    fma2(a0[0], wa0.x, d0); fma2(a0[1], wa0.x, d1);
                    fma2(a0[2], wa0.x, d2); fma2(a0[3], wa0.x, d3);
                    fma2(a1[0], wa1.x, d0); fma2(a1[1], wa1.x, d1);
                    fma2(a1[2], wa1.x, d2); fma2(a1[3], wa1.x, d3);
                }
                {   // k odd
                    ull d0 = pk2(qA.y, qA.y), d1 = pk2(qA.w, qA.w);
                    ull d2 = pk2(qB.y, qB.y), d3 = pk2(qB.w, qB.w);
                    fma2(a0[0], wa0.y, d0); fma2(a0[1], wa0.y, d1);
                    fma2(a0[2], wa0.y, d2); fma2(a0[3], wa0.y, d3);
                    fma2(a1[0], wa1.y, d0); fma2(a1[1], wa1.y, d1);
                    fma2(a1[2], wa1.y, d2); fma2(a1[3], wa1.y, d3);
                }
            }
            ulonglong2 wd0 = __ldg(Wb + (kb + n1) * HPAIR + hp0);
            ulonglong2 wd1 = __ldg(Wb + (kb + n1) * HPAIR + hp1);
            {
                const float4* hk =
                    reinterpret_cast<const float4*>(hd + (unsigned)(kb + c + 1) * 4);
                float4 qA = hk[0];
                float4 qB = hk[1];
                {   // k even
                    ull d0 = pk2(qA.x, qA.x), d1 = pk2(qA.z, qA.z);
                    ull d2 = pk2(qB.x, qB.x), d3 = pk2(qB.z, qB.z);
                    fma2(a0[0], wc0.x, d0); fma2(a0[1], wc0.x, d1);
                    fma2(a0[2], wc0.x, d2); fma2(a0[3], wc0.x, d3);
                    fma2(a1[0], wc1.x, d0); fma2(a1[1], wc1.x, d1);
                    fma2(a1[2], wc1.x, d2); fma2(a1[3], wc1.x, d3);
                }
                {   // k odd
                    ull d0 = pk2(qA.y, qA.y), d1 = pk2(qA.w, qA.w);
                    ull d2 = pk2(qB.y, qB.y), d3 = pk2(qB.w, qB.w);
                    fma2(a0[0], wc0.y, d0); fma2(a0[1], wc0.y, d1);
                    fma2(a0[2], wc0.y, d2); fma2(a0[3], wc0.y, d3);
                    fma2(a1[0], wc1.y, d0); fma2(a1[1], wc1.y, d1);
                    fma2(a1[2], wc1.y, d2); fma2(a1[3], wc1.y, d3);
                }
            }
            wa0 = wb0; wa1 = wb1; wc0 = wd0; wc1 = wd1;
        }

        // write partials: pB[hp][grp][b]
        *reinterpret_cast<ulonglong2*>(wr0)     = make_ulonglong2(a0[0], a0[1]);
        *reinterpret_cast<ulonglong2*>(wr0 + 2) = make_ulonglong2(a0[2], a0[3]);
        *reinterpret_cast<ulonglong2*>(wr1)     = make_ulonglong2(a1[0], a1[1]);
        *reinterpret_cast<ulonglong2*>(wr1 + 2) = make_ulonglong2(a1[2], a1[3]);
        __syncthreads();    // (2) partials visible; all hd reads complete

        // distributed epilogue: (h-pair ehp, batch eb)
        ull s = rd[0];
#pragma unroll
        for (int g = 1; g < 8; g++) {
            ull v = rd[g * 4];
            add2(s, s, v);
        }
        add2(s, s, pk2(pf.x, pf.y));

        float x0, x1;
        upk2(s, x0, x1);
        const float v0 = tanhf(x0);
        const float v1 = tanhf(x1);

        // non-duplicated state write: one STS.64 per thread
        hd[ehp * 4 + eb] = pk2(v0, v1);

        if (t == slen[eb] - 1)
            *reinterpret_cast<float2*>(g_last + orig[eb] * H + 2 * ehp) =
                make_float2(v0, v1);
    }
}

// ---------------------------------------------------------------------------
// Kernel: bucketed persistent RNN.
//   bid 0..103   : NB=4, rows 608 + 4*bid (longest 416 rows)
//   bid 104..179 : NB=8, rows 600 - 8*(bid-104) (descending; shortest last)
// ---------------------------------------------------------------------------
__global__ void __launch_bounds__(THR, 1) rnn_kernel(const int* __restrict__ x_in) {
    extern __shared__ char smem[];
    const int bid = blockIdx.x;
    if (bid < N_CTA4) {
        rnn_body4(x_in, 608 + 4 * bid, smem);
    } else {
        rnn_body8(x_in, 600 - 8 * (bid - N_CTA4), smem);
    }
}

// ---------------------------------------------------------------------------
// Kernel: MLP head — one rnn-style NB=8 step (relu) + k-split logits.
// ---------------------------------------------------------------------------
__global__ void __launch_bounds__(THR, 1) mlp_kernel(const float* __restrict__ b1,
                                                     const float* __restrict__ b2,
                                                     float* __restrict__ out) {
    extern __shared__ char smem[];
    ull*   hT2  = reinterpret_cast<ull*>(smem + MLP_HT2);    // [512][4]
    ull*   pB   = reinterpret_cast<ull*>(smem + MLP_PB);     // [256][34]
    float* hlin = reinterpret_cast<float*>(smem + MLP_HLIN); // [8][512]
    float* red  = reinterpret_cast<float*>(smem + MLP_RED);  // [256][5]

    const int tid  = threadIdx.x;
    const int grp  = tid >> 8;
    const int hp   = tid & (HPAIR - 1);
    const int base = blockIdx.x * BT;

    const int eh   = tid >> 1;
    const int eq   = tid & 1;
    const int ehp  = eh >> 1;
    const int epar = eh & 1;

    hT2[eh * 4 + 2 * eq + 0] = pk2(g_last[(base + 4 * eq + 0) * H + eh],
                                   g_last[(base + 4 * eq + 1) * H + eh]);
    hT2[eh * 4 + 2 * eq + 1] = pk2(g_last[(base + 4 * eq + 2) * H + eh],
                                   g_last[(base + 4 * eq + 3) * H + eh]);
    __syncthreads();

    const ulonglong2* Wp =
        reinterpret_cast<const ulonglong2*>(g_W1p) + (grp * 64) * HPAIR + hp;

    ull a0[4], a1[4];
#pragma unroll
    for (int p = 0; p < 4; p++) { a0[p] = 0ull; a1[p] = 0ull; }

    gemm_g6<8>(Wp, hT2, grp * 128, a0, a1);

    ull* myPB = pB + hp * 34 + grp * 8;
#pragma unroll
    for (int p = 0; p < 4; p += 2)
        *reinterpret_cast<ulonglong2*>(myPB + p) = make_ulonglong2(a0[p], a0[p + 1]);
#pragma unroll
    for (int p = 0; p < 4; p += 2)
        *reinterpret_cast<ulonglong2*>(myPB + 4 + p) = make_ulonglong2(a1[p], a1[p + 1]);
    __syncthreads();

    {
        const ull* ePB = pB + ehp * 34 + epar * 4 + eq * 2;
        ull s[2];
#pragma unroll
        for (int q = 0; q < 2; q++) s[q] = ePB[q];
#pragma unroll
        for (int g = 1; g < 4; g++) {
#pragma unroll
            for (int q = 0; q < 2; q++) {
                ull v = ePB[g * 8 + q];
                add2(s[q], s[q], v);
            }
        }
        const float bv = __ldg(b1 + eh);
#pragma unroll
        for (int q = 0; q < 2; q++) {
            float x, y;
            upk2(s[q], x, y);
            hlin[(eq * 4 + 2 * q + 0) * H + eh] = fmaxf(x + bv, 0.f);
            hlin[(eq * 4 + 2 * q + 1) * H + eh] = fmaxf(y + bv, 0.f);
        }
    }
    __syncthreads();

    {
        const int kq = tid >> 8;
        const int r  = tid & 255;
        const int b  = r >> 5;
        const int c  = r & 31;
        float acc = 0.f;
        const float* hb = hlin + b * H + kq * 128;
        const float* w2 = g_W2T + (kq * 128) * C + c;
#pragma unroll 8
        for (int k = 0; k < 128; k++) acc += hb[k] * __ldg(w2 + k * C);
        red[r * 5 + kq] = acc;
    }
    __syncthreads();

    if (tid < 256) {
        const int b = tid >> 5, c = tid & 31;
        float acc = __ldg(b2 + c) + red[tid * 5 + 0] + red[tid * 5 + 1]
                  + red[tid * 5 + 2] + red[tid * 5 + 3];
        out[(base + b) * C + c] = acc;
    }
}

// ---------------------------------------------------------------------------
extern "C" void kernel_launch(void* const* d_in, const int* in_sizes, int n_in,
                              void* d_out, int out_size) {
    const int*   x_in   = (const int*)  d_in[0];
    const int*   x_lens = (const int*)  d_in[1];
    const float* emb    = (const float*)d_in[2];
    const float* W_ih   = (const float*)d_in[3];
    const float* b_ih   = (const float*)d_in[4];
    const float* W_hh   = (const float*)d_in[5];
    const float* b_hh   = (const float*)d_in[6];
    const float* W1w    = (const float*)d_in[7];
    const float* b1     = (const float*)d_in[8];
    const float* W2w    = (const float*)d_in[9];
    const float* b2     = (const float*)d_in[10];
    float* out = (float*)d_out;

    cudaFuncSetAttribute(rnn_kernel,
                         cudaFuncAttributeMaxDynamicSharedMemorySize, RNN_SMEM);
    cudaFuncSetAttribute(mlp_kernel,
                         cudaFuncAttributeMaxDynamicSharedMemorySize, MLP_SMEM);

    setup_kernel<<<SETUP_GRID, 256>>>(x_lens, emb, W_ih, b_ih, b_hh,
                                      W_hh, W1w, W2w);
    rnn_kernel<<<RNN_GRID, THR, RNN_SMEM>>>(x_in);
    mlp_kernel<<<B / BT, THR, MLP_SMEM>>>(b1, b2, out);
}

// round 12
// speedup vs baseline: 1.0692x; 1.0009x over previous
#include <cuda_runtime.h>
#include <math.h>

// Problem dims (fixed by the dataset)
#define B 1024
#define S 64
#define E 256
#define H 512
#define V 128
#define C 32

#define BT    8
#define HPAIR 256          // h-pairs
#define THR   1024

// buckets: NB4 CTAs (longest rows, 608..1023), NB8 CTAs (rows 0..607 desc)
#define N_CTA4  104
#define N_CTA8  76
#define RNN_GRID (N_CTA4 + N_CTA8)   // 180

// dynamic smem (worst case = NB8 path): 16384 (state) + 69632 (partials) + ints
#define RNN_SMEM (16384 + 69632 + 96)

// mlp smem layout
#define MLP_HT2  0
#define MLP_PB   16384
#define MLP_HLIN 86016
#define MLP_RED  102400
#define MLP_SMEM (102400 + 5120)

// setup kernel block ranges (all 256-thread blocks)
//  [0,256)    : g_Wp   output float4s (65536, coalesced writes)
//  [256,512)  : g_W1p  output float4s (65536)
//  [512,528)  : g_W2T  output float4s (4096)
//  [528,656)  : P table (128 vocab rows)
//  [656,660)  : length sort (4 x 256 rows, lens staged in smem)
#define SETUP_WP_BLKS   256
#define SETUP_W2_BASE   512
#define SETUP_P_BASE    528
#define SETUP_SORT_BASE 656
#define SETUP_GRID      660

// Scratch (no allocations allowed -> __device__ globals)
__device__ float  g_P[V * H];                   // emb @ W_ih^T + b_ih + b_hh
__device__ float4 g_Wp[(H / 2) * (H / 2)];      // paired W_hh^T (1 MB)
__device__ float4 g_W1p[(H / 2) * (H / 2)];     // paired W1^T   (1 MB)
__device__ float  g_W2T[H * C];                 // W2^T [k][c]
__device__ float  g_last[B * H];                // h at t=len-1, original order
__device__ int    g_sidx[B];
__device__ int    g_slen[B];

// ---------------------------------------------------------------------------
// f32x2 helpers
// ---------------------------------------------------------------------------
typedef unsigned long long ull;
__device__ __forceinline__ ull pk2(float x, float y) {
    ull r; asm("mov.b64 %0, {%1, %2};" : "=l"(r) : "f"(x), "f"(y)); return r;
}
__device__ __forceinline__ void upk2(ull v, float& x, float& y) {
    asm("mov.b64 {%0, %1}, %2;" : "=f"(x), "=f"(y) : "l"(v));
}
__device__ __forceinline__ void fma2(ull& d, ull a, ull b) {
    asm("fma.rn.f32x2 %0, %1, %2, %3;" : "=l"(d) : "l"(a), "l"(b), "l"(d));
}
__device__ __forceinline__ void add2(ull& d, ull a, ull b) {
    asm("add.rn.f32x2 %0, %1, %2;" : "=l"(d) : "l"(a), "l"(b));
}

// ---------------------------------------------------------------------------
// Fused setup kernel (output-major / coalesced-write version).
// paired layout: g_Wp[kp*256+hp] = {W[2hp][2kp], W[2hp+1][2kp],
//                                   W[2hp][2kp+1], W[2hp+1][2kp+1]}
// (identical to previous rounds' layout: element (k&1)*2 + (h&1).)
// ---------------------------------------------------------------------------
__global__ void __launch_bounds__(256) setup_kernel(
        const int*   __restrict__ lens,
        const float* __restrict__ emb,
        const float* __restrict__ W_ih,
        const float* __restrict__ b_ih,
        const float* __restrict__ b_hh,
        const float* __restrict__ W_hh,
        const float* __restrict__ W1,
        const float* __restrict__ W2) {
    const int bid = blockIdx.x;
    const int tid = threadIdx.x;

    if (bid < 2 * SETUP_WP_BLKS) {
        // paired transpose of W_hh (bid<256) or W1 (bid in [256,512))
        const bool second = bid >= SETUP_WP_BLKS;
        const int  o  = (second ? bid - SETUP_WP_BLKS : bid) * 256 + tid; // 0..65535
        const int  hp = o & 255;
        const int  kp = o >> 8;
        const float2* src = reinterpret_cast<const float2*>(second ? W1 : W_hh);
        float2 r0 = __ldg(src + (2 * hp)     * (H / 2) + kp);  // row 2hp,  k=2kp..2kp+1
        float2 r1 = __ldg(src + (2 * hp + 1) * (H / 2) + kp);  // row 2hp+1
        float4 v = make_float4(r0.x, r1.x, r0.y, r1.y);
        (second ? g_W1p : g_Wp)[o] = v;                        // coalesced STG.128
    } else if (bid < SETUP_P_BASE) {
        // W2^T: output float4 q covers k = q>>3, c = (q&7)*4 .. +3
        const int q  = (bid - SETUP_W2_BASE) * 256 + tid;      // 0..4095
        const int k  = q >> 3;
        const int c0 = (q & 7) * 4;
        float4 v;
        v.x = __ldg(W2 + (c0 + 0) * H + k);
        v.y = __ldg(W2 + (c0 + 1) * H + k);
        v.z = __ldg(W2 + (c0 + 2) * H + k);
        v.w = __ldg(W2 + (c0 + 3) * H + k);
        reinterpret_cast<float4*>(g_W2T)[q] = v;               // coalesced
    } else if (bid < SETUP_SORT_BASE) {
        // P[v][h] = sum_e emb[v,e]*W_ih[h,e] + b_ih[h] + b_hh[h]; 256 thr, 2 h each
        __shared__ float es[E];
        const int v = bid - SETUP_P_BASE;
        es[tid] = emb[v * E + tid];
        __syncthreads();
        const float4* e4 = reinterpret_cast<const float4*>(es);
#pragma unroll
        for (int r = 0; r < 2; r++) {
            const int h = tid + r * 256;
            float acc = b_ih[h] + b_hh[h];
            const float4* w = reinterpret_cast<const float4*>(W_ih + h * E);
#pragma unroll 8
            for (int i = 0; i < E / 4; i++) {
                float4 a = e4[i], b = w[i];
                acc += a.x * b.x + a.y * b.y + a.z * b.z + a.w * b.w;
            }
            g_P[v * H + h] = acc;
        }
    } else {
        // stable rank sort by length; lens staged through smem
        __shared__ int sl[B];
        for (int j = tid; j < B; j += 256) sl[j] = __ldg(lens + j);
        __syncthreads();
        const int i  = (bid - SETUP_SORT_BASE) * 256 + tid;
        const int my = sl[i];
        int rank = 0;
#pragma unroll 8
        for (int j = 0; j < B; j++) {
            int lj = sl[j];
            rank += (lj < my) || (lj == my && j < i);
        }
        g_sidx[rank] = i;
        g_slen[rank] = my;
    }
}

// ---------------------------------------------------------------------------
// Packed-batch inner compute (NB8 + mlp): 4 kp (8 k), weights in regs.
// hT2 (ull view): [k][NB/2] — pair p holds batches (2p, 2p+1).
// ---------------------------------------------------------------------------
template <int NB>
__device__ __forceinline__ void comp4T(const ull* __restrict__ hT2, int k0,
                                       const ulonglong2 w[4],
                                       ull* __restrict__ a0, ull* __restrict__ a1) {
#pragma unroll
    for (int j = 0; j < 4; j++) {
#pragma unroll
        for (int kk = 0; kk < 2; kk++) {
            const int k = k0 + 2 * j + kk;
            float wl, wh;
            upk2(kk ? w[j].y : w[j].x, wl, wh);
            ull s0 = pk2(wl, wl), s1 = pk2(wh, wh);
            const ulonglong2* hk =
                reinterpret_cast<const ulonglong2*>(hT2 + (unsigned)k * (NB / 2));
#pragma unroll
            for (int p = 0; p < NB / 4; p++) {
                ulonglong2 hv = hk[p];
                fma2(a0[2 * p], hv.x, s0); fma2(a0[2 * p + 1], hv.y, s0);
                fma2(a1[2 * p], hv.x, s1); fma2(a1[2 * p + 1], hv.y, s1);
            }
        }
    }
}

// 64-kp GEMM pass: 8-kp chunks, double-buffered W prefetch
template <int NB>
__device__ __forceinline__ void gemm_g6(const ulonglong2* __restrict__ Wp,
                                        const ull* __restrict__ hT2, int kbase,
                                        ull* __restrict__ a0, ull* __restrict__ a1) {
    ulonglong2 wA[4], wB[4];
#pragma unroll
    for (int j = 0; j < 4; j++) wA[j] = __ldg(Wp + j * HPAIR);
#pragma unroll 1
    for (int c = 0; c < 64; c += 8) {
#pragma unroll
        for (int j = 0; j < 4; j++) wB[j] = __ldg(Wp + (c + 4 + j) * HPAIR);
        comp4T<NB>(hT2, kbase + 2 * c, wA, a0, a1);
        const int nc = (c + 8) & 63;        // wrap dummy on last iter
#pragma unroll
        for (int j = 0; j < 4; j++) wA[j] = __ldg(Wp + (nc + j) * HPAIR);
        comp4T<NB>(hT2, kbase + 2 * (c + 4), wB, a0, a1);
    }
}

// ---------------------------------------------------------------------------
// NB=8 RNN body (proven round-6 version): 4-way k-split, packed-batch state.
// ---------------------------------------------------------------------------
__device__ __forceinline__ void rnn_body8(const int* __restrict__ x_in,
                                          int rowbase, char* smem) {
    constexpr int NB = 8;
    constexpr int PBS = 34;
    ull* hT2 = reinterpret_cast<ull*>(smem);                   // [512][4]
    ull* pB  = hT2 + 512 * 4;                                  // [256][34]
    int* ints = reinterpret_cast<int*>(pB + 256 * PBS);
    int* orig = ints;
    int* slen = ints + NB;
    int* xi   = ints + 2 * NB;

    const int tid = threadIdx.x;
    const int grp = tid >> 8;
    const int hp  = tid & (HPAIR - 1);

    const int eh   = tid >> 1;
    const int eq   = tid & 1;
    const int ehp  = eh >> 1;
    const int epar = eh & 1;

    if (tid < NB) {
        orig[tid] = g_sidx[rowbase + tid];
        slen[tid] = g_slen[rowbase + tid];
    }
    for (int i = tid; i < 512 * 4; i += THR) hT2[i] = 0ull;
    __syncthreads();

    int tmax = 0;
#pragma unroll
    for (int b = 0; b < NB; b++) tmax = max(tmax, slen[b]);

    const ulonglong2* Wp =
        reinterpret_cast<const ulonglong2*>(g_Wp) + (grp * 64) * HPAIR + hp;
    const int kbase = grp * 128;

    ull*       myPB = pB + hp * PBS + grp * NB;
    const ull* ePB  = pB + ehp * PBS + epar * 4 + eq * 2;

    for (int t = 0; t < tmax; t++) {
        if (tid < NB) xi[tid] = x_in[orig[tid] * S + t];
        __syncthreads();

        float pf[4];
#pragma unroll
        for (int i = 0; i < 4; i++)
            pf[i] = __ldg(g_P + xi[eq * 4 + i] * H + eh);

        ull a0[4], a1[4];
#pragma unroll
        for (int p = 0; p < 4; p++) { a0[p] = 0ull; a1[p] = 0ull; }

        gemm_g6<8>(Wp, hT2, kbase, a0, a1);

#pragma unroll
        for (int p = 0; p < 4; p += 2)
            *reinterpret_cast<ulonglong2*>(myPB + p) =
                make_ulonglong2(a0[p], a0[p + 1]);
#pragma unroll
        for (int p = 0; p < 4; p += 2)
            *reinterpret_cast<ulonglong2*>(myPB + 4 + p) =
                make_ulonglong2(a1[p], a1[p + 1]);
        __syncthreads();

        ull s[2];
#pragma unroll
        for (int q = 0; q < 2; q++) s[q] = ePB[q];
#pragma unroll
        for (int g = 1; g < 4; g++) {
#pragma unroll
            for (int q = 0; q < 2; q++) {
                ull v = ePB[g * NB + q];
                add2(s[q], s[q], v);
            }
        }
#pragma unroll
        for (int q = 0; q < 2; q++)
            add2(s[q], s[q], pk2(pf[2 * q], pf[2 * q + 1]));

        float v[4];
#pragma unroll
        for (int q = 0; q < 2; q++) {
            float x, y;
            upk2(s[q], x, y);
            v[2 * q]     = tanhf(x);
            v[2 * q + 1] = tanhf(y);
        }
#pragma unroll
        for (int q = 0; q < 2; q++)
            hT2[eh * 4 + eq * 2 + q] = pk2(v[2 * q], v[2 * q + 1]);

#pragma unroll
        for (int i = 0; i < 4; i++) {
            const int b = eq * 4 + i;
            if (t == slen[b] - 1) g_last[orig[b] * H + eh] = v[i];
        }
    }
}

// ---------------------------------------------------------------------------
// NB=4 RNN body — non-duplicated state, minimal LDS traffic.
// 8-way k-split; thread owns h-pairs hp0 = tid&127 and hp1 = hp0+128.
// State hd[kp][b] = float2(h[2kp], h[2kp+1])  (8 B per (kp,b); 8 KB total).
// ---------------------------------------------------------------------------
__device__ __forceinline__ void rnn_body4(const int* __restrict__ x_in,
                                          int rowbase, char* smem) {
    ull* hd = reinterpret_cast<ull*>(smem);                    // [256][4] float2
    ull* pB = hd + 256 * 4;                                    // [256][34]
    int* ints = reinterpret_cast<int*>(pB + 256 * 34);
    int* orig = ints;
    int* slen = ints + 4;
    int* xi   = ints + 8;

    const int tid = threadIdx.x;
    const int grp = tid >> 7;              // 0..7
    const int u   = tid & 127;
    const int hp0 = u;
    const int hp1 = u + 128;

    // epilogue role: thread = (h-pair ehp, batch eb)
    const int ehp = tid >> 2;              // 0..255
    const int eb  = tid & 3;

    if (tid < 4) {
        orig[tid] = g_sidx[rowbase + tid];
        slen[tid] = g_slen[rowbase + tid];
    }
    for (int i = tid; i < 256 * 4; i += THR) hd[i] = 0ull;
    __syncthreads();

    int tmax = 0;
#pragma unroll
    for (int b = 0; b < 4; b++) tmax = max(tmax, slen[b]);

    const ulonglong2* Wb = reinterpret_cast<const ulonglong2*>(g_Wp);
    const int kb = grp * 32;               // kp base for this group

    ull*       wr0 = pB + hp0 * 34 + grp * 4;
    ull*       wr1 = pB + hp1 * 34 + grp * 4;
    const ull* rd  = pB + ehp * 34 + eb;

    for (int t = 0; t < tmax; t++) {
        if (tid < 4) xi[tid] = x_in[orig[tid] * S + t];
        __syncthreads();    // (1) xi ready; hd from previous epilogue visible

        float2 pf = __ldg(reinterpret_cast<const float2*>(g_P + xi[eb] * H) + ehp);

        ull a0[4], a1[4];
#pragma unroll
        for (int b = 0; b < 4; b++) { a0[b] = 0ull; a1[b] = 0ull; }

        // 32 kp, 2-kp unrolled, double-buffered W prefetch
        ulonglong2 wa0 = __ldg(Wb + (kb + 0) * HPAIR + hp0);
        ulonglong2 wa1 = __ldg(Wb + (kb + 0) * HPAIR + hp1);
        ulonglong2 wc0 = __ldg(Wb + (kb + 1) * HPAIR + hp0);
        ulonglong2 wc1 = __ldg(Wb + (kb + 1) * HPAIR + hp1);
#pragma unroll 4
        for (int c = 0; c < 32; c += 2) {
            const int n0 = (c + 2) & 31;
            const int n1 = (c + 3) & 31;
            ulonglong2 wb0 = __ldg(Wb + (kb + n0) * HPAIR + hp0);
            ulonglong2 wb1 = __ldg(Wb + (kb + n0) * HPAIR + hp1);
            {
                const float4* hk =
                    reinterpret_cast<const float4*>(hd + (unsigned)(kb + c) * 4);
                float4 qA = hk[0];   // b0:(ke,ko), b1:(ke,ko)
                float4 qB = hk[1];   // b2:(ke,ko), b3:(ke,ko)
                {   // k even
                    ull d0 = pk2(qA.x, qA.x), d1 = pk2(qA.z, qA.z);
                    ull d2 = pk2(qB.x, qB.x), d3 = pk2(qB.z, qB.z);
                    fma2(a0[0], wa0.x, d0); fma2(a0[1], wa0.x, d1);
                    fma2(a0[2], wa0.x, d2); fma2(a0[3], wa0.x, d3);
                    fma2(a1[0], wa1.x, d0); fma2(a1[1], wa1.x, d1);
                    fma2(a1[2], wa1.x, d2); fma2(a1[3], wa1.x, d3);
                }
                {   // k odd
                    ull d0 = pk2(qA.y, qA.y), d1 = pk2(qA.w, qA.w);
                    ull d2 = pk2(qB.y, qB.y), d3 = pk2(qB.w, qB.w);
                    fma2(a0[0], wa0.y, d0); fma2(a0[1], wa0.y, d1);
                    fma2(a0[2], wa0.y, d2); fma2(a0[3], wa0.y, d3);
                    fma2(a1[0], wa1.y, d0); fma2(a1[1], wa1.y, d1);
                    fma2(a1[2], wa1.y, d2); fma2(a1[3], wa1.y, d3);
                }
            }
            ulonglong2 wd0 = __ldg(Wb + (kb + n1) * HPAIR + hp0);
            ulonglong2 wd1 = __ldg(Wb + (kb + n1) * HPAIR + hp1);
            {
                const float4* hk =
                    reinterpret_cast<const float4*>(hd + (unsigned)(kb + c + 1) * 4);
                float4 qA = hk[0];
                float4 qB = hk[1];
                {   // k even
                    ull d0 = pk2(qA.x, qA.x), d1 = pk2(qA.z, qA.z);
                    ull d2 = pk2(qB.x, qB.x), d3 = pk2(qB.z, qB.z);
                    fma2(a0[0], wc0.x, d0); fma2(a0[1], wc0.x, d1);
                    fma2(a0[2], wc0.x, d2); fma2(a0[3], wc0.x, d3);
                    fma2(a1[0], wc1.x, d0); fma2(a1[1], wc1.x, d1);
                    fma2(a1[2], wc1.x, d2); fma2(a1[3], wc1.x, d3);
                }
                {   // k odd
                    ull d0 = pk2(qA.y, qA.y), d1 = pk2(qA.w, qA.w);
                    ull d2 = pk2(qB.y, qB.y), d3 = pk2(qB.w, qB.w);
                    fma2(a0[0], wc0.y, d0); fma2(a0[1], wc0.y, d1);
                    fma2(a0[2], wc0.y, d2); fma2(a0[3], wc0.y, d3);
                    fma2(a1[0], wc1.y, d0); fma2(a1[1], wc1.y, d1);
                    fma2(a1[2], wc1.y, d2); fma2(a1[3], wc1.y, d3);
                }
            }
            wa0 = wb0; wa1 = wb1; wc0 = wd0; wc1 = wd1;
        }

        // write partials: pB[hp][grp][b]
        *reinterpret_cast<ulonglong2*>(wr0)     = make_ulonglong2(a0[0], a0[1]);
        *reinterpret_cast<ulonglong2*>(wr0 + 2) = make_ulonglong2(a0[2], a0[3]);
        *reinterpret_cast<ulonglong2*>(wr1)     = make_ulonglong2(a1[0], a1[1]);
        *reinterpret_cast<ulonglong2*>(wr1 + 2) = make_ulonglong2(a1[2], a1[3]);
        __syncthreads();    // (2) partials visible; all hd reads complete

        // distributed epilogue: (h-pair ehp, batch eb)
        ull s = rd[0];
#pragma unroll
        for (int g = 1; g < 8; g++) {
            ull v = rd[g * 4];
            add2(s, s, v);
        }
        add2(s, s, pk2(pf.x, pf.y));

        float x0, x1;
        upk2(s, x0, x1);
        const float v0 = tanhf(x0);
        const float v1 = tanhf(x1);

        // non-duplicated state write: one STS.64 per thread
        hd[ehp * 4 + eb] = pk2(v0, v1);

        if (t == slen[eb] - 1)
            *reinterpret_cast<float2*>(g_last + orig[eb] * H + 2 * ehp) =
                make_float2(v0, v1);
    }
}

// ---------------------------------------------------------------------------
// Kernel: bucketed persistent RNN.
//   bid 0..103   : NB=4, rows 608 + 4*bid (longest 416 rows)
//   bid 104..179 : NB=8, rows 600 - 8*(bid-104) (descending; shortest last)
// ---------------------------------------------------------------------------
__global__ void __launch_bounds__(THR, 1) rnn_kernel(const int* __restrict__ x_in) {
    extern __shared__ char smem[];
    const int bid = blockIdx.x;
    if (bid < N_CTA4) {
        rnn_body4(x_in, 608 + 4 * bid, smem);
    } else {
        rnn_body8(x_in, 600 - 8 * (bid - N_CTA4), smem);
    }
}

// ---------------------------------------------------------------------------
// Kernel: MLP head — one rnn-style NB=8 step (relu) + k-split logits.
// ---------------------------------------------------------------------------
__global__ void __launch_bounds__(THR, 1) mlp_kernel(const float* __restrict__ b1,
                                                     const float* __restrict__ b2,
                                                     float* __restrict__ out) {
    extern __shared__ char smem[];
    ull*   hT2  = reinterpret_cast<ull*>(smem + MLP_HT2);    // [512][4]
    ull*   pB   = reinterpret_cast<ull*>(smem + MLP_PB);     // [256][34]
    float* hlin = reinterpret_cast<float*>(smem + MLP_HLIN); // [8][512]
    float* red  = reinterpret_cast<float*>(smem + MLP_RED);  // [256][5]

    const int tid  = threadIdx.x;
    const int grp  = tid >> 8;
    const int hp   = tid & (HPAIR - 1);
    const int base = blockIdx.x * BT;

    const int eh   = tid >> 1;
    const int eq   = tid & 1;
    const int ehp  = eh >> 1;
    const int epar = eh & 1;

    hT2[eh * 4 + 2 * eq + 0] = pk2(g_last[(base + 4 * eq + 0) * H + eh],
                                   g_last[(base + 4 * eq + 1) * H + eh]);
    hT2[eh * 4 + 2 * eq + 1] = pk2(g_last[(base + 4 * eq + 2) * H + eh],
                                   g_last[(base + 4 * eq + 3) * H + eh]);
    __syncthreads();

    const ulonglong2* Wp =
        reinterpret_cast<const ulonglong2*>(g_W1p) + (grp * 64) * HPAIR + hp;

    ull a0[4], a1[4];
#pragma unroll
    for (int p = 0; p < 4; p++) { a0[p] = 0ull; a1[p] = 0ull; }

    gemm_g6<8>(Wp, hT2, grp * 128, a0, a1);

    ull* myPB = pB + hp * 34 + grp * 8;
#pragma unroll
    for (int p = 0; p < 4; p += 2)
        *reinterpret_cast<ulonglong2*>(myPB + p) = make_ulonglong2(a0[p], a0[p + 1]);
#pragma unroll
    for (int p = 0; p < 4; p += 2)
        *reinterpret_cast<ulonglong2*>(myPB + 4 + p) = make_ulonglong2(a1[p], a1[p + 1]);
    __syncthreads();

    {
        const ull* ePB = pB + ehp * 34 + epar * 4 + eq * 2;
        ull s[2];
#pragma unroll
        for (int q = 0; q < 2; q++) s[q] = ePB[q];
#pragma unroll
        for (int g = 1; g < 4; g++) {
#pragma unroll
            for (int q = 0; q < 2; q++) {
                ull v = ePB[g * 8 + q];
                add2(s[q], s[q], v);
            }
        }
        const float bv = __ldg(b1 + eh);
#pragma unroll
        for (int q = 0; q < 2; q++) {
            float x, y;
            upk2(s[q], x, y);
            hlin[(eq * 4 + 2 * q + 0) * H + eh] = fmaxf(x + bv, 0.f);
            hlin[(eq * 4 + 2 * q + 1) * H + eh] = fmaxf(y + bv, 0.f);
        }
    }
    __syncthreads();

    {
        const int kq = tid >> 8;
        const int r  = tid & 255;
        const int b  = r >> 5;
        const int c  = r & 31;
        float acc = 0.f;
        const float* hb = hlin + b * H + kq * 128;
        const float* w2 = g_W2T + (kq * 128) * C + c;
#pragma unroll 8
        for (int k = 0; k < 128; k++) acc += hb[k] * __ldg(w2 + k * C);
        red[r * 5 + kq] = acc;
    }
    __syncthreads();

    if (tid < 256) {
        const int b = tid >> 5, c = tid & 31;
        float acc = __ldg(b2 + c) + red[tid * 5 + 0] + red[tid * 5 + 1]
                  + red[tid * 5 + 2] + red[tid * 5 + 3];
        out[(base + b) * C + c] = acc;
    }
}

// ---------------------------------------------------------------------------
extern "C" void kernel_launch(void* const* d_in, const int* in_sizes, int n_in,
                              void* d_out, int out_size) {
    const int*   x_in   = (const int*)  d_in[0];
    const int*   x_lens = (const int*)  d_in[1];
    const float* emb    = (const float*)d_in[2];
    const float* W_ih   = (const float*)d_in[3];
    const float* b_ih   = (const float*)d_in[4];
    const float* W_hh   = (const float*)d_in[5];
    const float* b_hh   = (const float*)d_in[6];
    const float* W1w    = (const float*)d_in[7];
    const float* b1     = (const float*)d_in[8];
    const float* W2w    = (const float*)d_in[9];
    const float* b2     = (const float*)d_in[10];
    float* out = (float*)d_out;

    cudaFuncSetAttribute(rnn_kernel,
                         cudaFuncAttributeMaxDynamicSharedMemorySize, RNN_SMEM);
    cudaFuncSetAttribute(mlp_kernel,
                         cudaFuncAttributeMaxDynamicSharedMemorySize, MLP_SMEM);

    setup_kernel<<<SETUP_GRID, 256>>>(x_lens, emb, W_ih, b_ih, b_hh,
                                      W_hh, W1w, W2w);
    rnn_kernel<<<RNN_GRID, THR, RNN_SMEM>>>(x_in);
    mlp_kernel<<<B / BT, THR, MLP_SMEM>>>(b1, b2, out);
}

// round 13
// speedup vs baseline: 1.1002x; 1.0290x over previous
#include <cuda_runtime.h>
#include <math.h>

// Problem dims (fixed by the dataset)
#define B 1024
#define S 64
#define E 256
#define H 512
#define V 128
#define C 32

#define BT    8
#define HPAIR 256          // h-pairs
#define THR   1024

// buckets: NB4 CTAs (longest rows, 608..1023), NB8 CTAs (rows 0..607 desc)
#define N_CTA4  104
#define N_CTA8  76
#define RNN_GRID (N_CTA4 + N_CTA8)   // 180

// dynamic smem (worst case = NB8 path): 16384 (state) + 69632 (partials) + ints
#define RNN_SMEM (16384 + 69632 + 96)

// mlp smem layout
#define MLP_HT2  0
#define MLP_PB   16384
#define MLP_HLIN 86016
#define MLP_RED  102400
#define MLP_SMEM (102400 + 5120)

// setup kernel block ranges (all 256-thread blocks)
//  [0,128)    : smem-tiled paired transpose (64 blocks W_hh, 64 blocks W1)
//  [128,144)  : g_W2T  output float4s (4096)
//  [144,272)  : P table (128 vocab rows)
//  [272,276)  : length sort (4 x 256 rows, lens staged in smem)
#define SETUP_TR_BLKS   128
#define SETUP_W2_BASE   128
#define SETUP_P_BASE    144
#define SETUP_SORT_BASE 272
#define SETUP_GRID      276

// Scratch (no allocations allowed -> __device__ globals)
__device__ float  g_P[V * H];                   // emb @ W_ih^T + b_ih + b_hh
__device__ float4 g_Wp[(H / 2) * (H / 2)];      // paired W_hh^T (1 MB)
__device__ float4 g_W1p[(H / 2) * (H / 2)];     // paired W1^T   (1 MB)
__device__ float  g_W2T[H * C];                 // W2^T [k][c]
__device__ float  g_last[B * H];                // h at t=len-1, original order
__device__ int    g_sidx[B];
__device__ int    g_slen[B];

// ---------------------------------------------------------------------------
// f32x2 helpers
// ---------------------------------------------------------------------------
typedef unsigned long long ull;
__device__ __forceinline__ ull pk2(float x, float y) {
    ull r; asm("mov.b64 %0, {%1, %2};" : "=l"(r) : "f"(x), "f"(y)); return r;
}
__device__ __forceinline__ void upk2(ull v, float& x, float& y) {
    asm("mov.b64 {%0, %1}, %2;" : "=f"(x), "=f"(y) : "l"(v));
}
__device__ __forceinline__ void fma2(ull& d, ull a, ull b) {
    asm("fma.rn.f32x2 %0, %1, %2, %3;" : "=l"(d) : "l"(a), "l"(b), "l"(d));
}
__device__ __forceinline__ void add2(ull& d, ull a, ull b) {
    asm("add.rn.f32x2 %0, %1, %2;" : "=l"(d) : "l"(a), "l"(b));
}

// ---------------------------------------------------------------------------
// Fused setup kernel v3: smem-tiled transpose (coalesced reads AND writes).
// paired layout (unchanged): g_Wp[kp*256+hp] =
//   {W[2hp][2kp], W[2hp+1][2kp], W[2hp][2kp+1], W[2hp+1][2kp+1]}
// ---------------------------------------------------------------------------
__global__ void __launch_bounds__(256) setup_kernel(
        const int*   __restrict__ lens,
        const float* __restrict__ emb,
        const float* __restrict__ W_ih,
        const float* __restrict__ b_ih,
        const float* __restrict__ b_hh,
        const float* __restrict__ W_hh,
        const float* __restrict__ W1,
        const float* __restrict__ W2) {
    const int bid = blockIdx.x;
    const int tid = threadIdx.x;

    if (bid < SETUP_TR_BLKS) {
        // tiled paired transpose: 64 tiles per matrix, tile = 64 h x 64 k
        __shared__ float ts[64][65];            // padded
        const int  m  = bid >> 6;               // 0: W_hh, 1: W1
        const int  tb = bid & 63;
        const int  th = tb & 7;                 // h-tile
        const int  tk = tb >> 3;                // k-tile
        const float* src = m ? W1 : W_hh;

        // load 64x64 tile, fully coalesced (16 float4 per row)
#pragma unroll
        for (int j = 0; j < 4; j++) {
            const int idx = tid + j * 256;      // 0..1023
            const int row = idx >> 4;
            const int c4  = idx & 15;
            float4 v = __ldg(reinterpret_cast<const float4*>(
                                 src + (64 * th + row) * H + 64 * tk) + c4);
            ts[row][4 * c4 + 0] = v.x;
            ts[row][4 * c4 + 1] = v.y;
            ts[row][4 * c4 + 2] = v.z;
            ts[row][4 * c4 + 3] = v.w;
        }
        __syncthreads();

        // write paired layout, coalesced (512B runs per kp row)
        float4* dst = m ? g_W1p : g_Wp;
#pragma unroll
        for (int j = 0; j < 4; j++) {
            const int idx  = tid + j * 256;     // 0..1023
            const int kp_l = idx >> 5;          // 0..31
            const int hp_l = idx & 31;
            const int lh = 2 * hp_l, lk = 2 * kp_l;
            float4 v = make_float4(ts[lh][lk],     ts[lh + 1][lk],
                                   ts[lh][lk + 1], ts[lh + 1][lk + 1]);
            dst[(32 * tk + kp_l) * 256 + (32 * th + hp_l)] = v;
        }
    } else if (bid < SETUP_P_BASE) {
        // W2^T: output float4 q covers k = q>>3, c = (q&7)*4 .. +3
        const int q  = (bid - SETUP_W2_BASE) * 256 + tid;      // 0..4095
        const int k  = q >> 3;
        const int c0 = (q & 7) * 4;
        float4 v;
        v.x = __ldg(W2 + (c0 + 0) * H + k);
        v.y = __ldg(W2 + (c0 + 1) * H + k);
        v.z = __ldg(W2 + (c0 + 2) * H + k);
        v.w = __ldg(W2 + (c0 + 3) * H + k);
        reinterpret_cast<float4*>(g_W2T)[q] = v;               // coalesced
    } else if (bid < SETUP_SORT_BASE) {
        // P[v][h] = sum_e emb[v,e]*W_ih[h,e] + b_ih[h] + b_hh[h]; 256 thr, 2 h each
        __shared__ float es[E];
        const int v = bid - SETUP_P_BASE;
        es[tid] = emb[v * E + tid];
        __syncthreads();
        const float4* e4 = reinterpret_cast<const float4*>(es);
#pragma unroll
        for (int r = 0; r < 2; r++) {
            const int h = tid + r * 256;
            float acc = b_ih[h] + b_hh[h];
            const float4* w = reinterpret_cast<const float4*>(W_ih + h * E);
#pragma unroll 8
            for (int i = 0; i < E / 4; i++) {
                float4 a = e4[i], b = w[i];
                acc += a.x * b.x + a.y * b.y + a.z * b.z + a.w * b.w;
            }
            g_P[v * H + h] = acc;
        }
    } else {
        // stable rank sort by length; lens staged through smem
        __shared__ int sl[B];
        for (int j = tid; j < B; j += 256) sl[j] = __ldg(lens + j);
        __syncthreads();
        const int i  = (bid - SETUP_SORT_BASE) * 256 + tid;
        const int my = sl[i];
        int rank = 0;
#pragma unroll 8
        for (int j = 0; j < B; j++) {
            int lj = sl[j];
            rank += (lj < my) || (lj == my && j < i);
        }
        g_sidx[rank] = i;
        g_slen[rank] = my;
    }
}

// ---------------------------------------------------------------------------
// Packed-batch inner compute (NB8 + mlp): 4 kp (8 k), weights in regs.
// hT2 (ull view): [k][NB/2] — pair p holds batches (2p, 2p+1).
// ---------------------------------------------------------------------------
template <int NB>
__device__ __forceinline__ void comp4T(const ull* __restrict__ hT2, int k0,
                                       const ulonglong2 w[4],
                                       ull* __restrict__ a0, ull* __restrict__ a1) {
#pragma unroll
    for (int j = 0; j < 4; j++) {
#pragma unroll
        for (int kk = 0; kk < 2; kk++) {
            const int k = k0 + 2 * j + kk;
            float wl, wh;
            upk2(kk ? w[j].y : w[j].x, wl, wh);
            ull s0 = pk2(wl, wl), s1 = pk2(wh, wh);
            const ulonglong2* hk =
                reinterpret_cast<const ulonglong2*>(hT2 + (unsigned)k * (NB / 2));
#pragma unroll
            for (int p = 0; p < NB / 4; p++) {
                ulonglong2 hv = hk[p];
                fma2(a0[2 * p], hv.x, s0); fma2(a0[2 * p + 1], hv.y, s0);
                fma2(a1[2 * p], hv.x, s1); fma2(a1[2 * p + 1], hv.y, s1);
            }
        }
    }
}

// 64-kp GEMM pass: 8-kp chunks, double-buffered W prefetch
template <int NB>
__device__ __forceinline__ void gemm_g6(const ulonglong2* __restrict__ Wp,
                                        const ull* __restrict__ hT2, int kbase,
                                        ull* __restrict__ a0, ull* __restrict__ a1) {
    ulonglong2 wA[4], wB[4];
#pragma unroll
    for (int j = 0; j < 4; j++) wA[j] = __ldg(Wp + j * HPAIR);
#pragma unroll 1
    for (int c = 0; c < 64; c += 8) {
#pragma unroll
        for (int j = 0; j < 4; j++) wB[j] = __ldg(Wp + (c + 4 + j) * HPAIR);
        comp4T<NB>(hT2, kbase + 2 * c, wA, a0, a1);
        const int nc = (c + 8) & 63;        // wrap dummy on last iter
#pragma unroll
        for (int j = 0; j < 4; j++) wA[j] = __ldg(Wp + (nc + j) * HPAIR);
        comp4T<NB>(hT2, kbase + 2 * (c + 4), wB, a0, a1);
    }
}

// ---------------------------------------------------------------------------
// NB=8 RNN body (proven round-6 version): 4-way k-split, packed-batch state.
// ---------------------------------------------------------------------------
__device__ __forceinline__ void rnn_body8(const int* __restrict__ x_in,
                                          int rowbase, char* smem) {
    constexpr int NB = 8;
    constexpr int PBS = 34;
    ull* hT2 = reinterpret_cast<ull*>(smem);                   // [512][4]
    ull* pB  = hT2 + 512 * 4;                                  // [256][34]
    int* ints = reinterpret_cast<int*>(pB + 256 * PBS);
    int* orig = ints;
    int* slen = ints + NB;
    int* xi   = ints + 2 * NB;

    const int tid = threadIdx.x;
    const int grp = tid >> 8;
    const int hp  = tid & (HPAIR - 1);

    const int eh   = tid >> 1;
    const int eq   = tid & 1;
    const int ehp  = eh >> 1;
    const int epar = eh & 1;

    if (tid < NB) {
        orig[tid] = g_sidx[rowbase + tid];
        slen[tid] = g_slen[rowbase + tid];
    }
    for (int i = tid; i < 512 * 4; i += THR) hT2[i] = 0ull;
    __syncthreads();

    int tmax = 0;
#pragma unroll
    for (int b = 0; b < NB; b++) tmax = max(tmax, slen[b]);

    const ulonglong2* Wp =
        reinterpret_cast<const ulonglong2*>(g_Wp) + (grp * 64) * HPAIR + hp;
    const int kbase = grp * 128;

    ull*       myPB = pB + hp * PBS + grp * NB;
    const ull* ePB  = pB + ehp * PBS + epar * 4 + eq * 2;

    for (int t = 0; t < tmax; t++) {
        if (tid < NB) xi[tid] = x_in[orig[tid] * S + t];
        __syncthreads();

        float pf[4];
#pragma unroll
        for (int i = 0; i < 4; i++)
            pf[i] = __ldg(g_P + xi[eq * 4 + i] * H + eh);

        ull a0[4], a1[4];
#pragma unroll
        for (int p = 0; p < 4; p++) { a0[p] = 0ull; a1[p] = 0ull; }

        gemm_g6<8>(Wp, hT2, kbase, a0, a1);

#pragma unroll
        for (int p = 0; p < 4; p += 2)
            *reinterpret_cast<ulonglong2*>(myPB + p) =
                make_ulonglong2(a0[p], a0[p + 1]);
#pragma unroll
        for (int p = 0; p < 4; p += 2)
            *reinterpret_cast<ulonglong2*>(myPB + 4 + p) =
                make_ulonglong2(a1[p], a1[p + 1]);
        __syncthreads();

        ull s[2];
#pragma unroll
        for (int q = 0; q < 2; q++) s[q] = ePB[q];
#pragma unroll
        for (int g = 1; g < 4; g++) {
#pragma unroll
            for (int q = 0; q < 2; q++) {
                ull v = ePB[g * NB + q];
                add2(s[q], s[q], v);
            }
        }
#pragma unroll
        for (int q = 0; q < 2; q++)
            add2(s[q], s[q], pk2(pf[2 * q], pf[2 * q + 1]));

        float v[4];
#pragma unroll
        for (int q = 0; q < 2; q++) {
            float x, y;
            upk2(s[q], x, y);
            v[2 * q]     = tanhf(x);
            v[2 * q + 1] = tanhf(y);
        }
#pragma unroll
        for (int q = 0; q < 2; q++)
            hT2[eh * 4 + eq * 2 + q] = pk2(v[2 * q], v[2 * q + 1]);

#pragma unroll
        for (int i = 0; i < 4; i++) {
            const int b = eq * 4 + i;
            if (t == slen[b] - 1) g_last[orig[b] * H + eh] = v[i];
        }
    }
}

// ---------------------------------------------------------------------------
// NB=4 RNN body — non-duplicated state, minimal LDS traffic.
// 8-way k-split; thread owns h-pairs hp0 = tid&127 and hp1 = hp0+128.
// State hd[kp][b] = float2(h[2kp], h[2kp+1])  (8 B per (kp,b); 8 KB total).
// ---------------------------------------------------------------------------
__device__ __forceinline__ void rnn_body4(const int* __restrict__ x_in,
                                          int rowbase, char* smem) {
    ull* hd = reinterpret_cast<ull*>(smem);                    // [256][4] float2
    ull* pB = hd + 256 * 4;                                    // [256][34]
    int* ints = reinterpret_cast<int*>(pB + 256 * 34);
    int* orig = ints;
    int* slen = ints + 4;
    int* xi   = ints + 8;

    const int tid = threadIdx.x;
    const int grp = tid >> 7;              // 0..7
    const int u   = tid & 127;
    const int hp0 = u;
    const int hp1 = u + 128;

    // epilogue role: thread = (h-pair ehp, batch eb)
    const int ehp = tid >> 2;              // 0..255
    const int eb  = tid & 3;

    if (tid < 4) {
        orig[tid] = g_sidx[rowbase + tid];
        slen[tid] = g_slen[rowbase + tid];
    }
    for (int i = tid; i < 256 * 4; i += THR) hd[i] = 0ull;
    __syncthreads();

    int tmax = 0;
#pragma unroll
    for (int b = 0; b < 4; b++) tmax = max(tmax, slen[b]);

    const ulonglong2* Wb = reinterpret_cast<const ulonglong2*>(g_Wp);
    const int kb = grp * 32;               // kp base for this group

    ull*       wr0 = pB + hp0 * 34 + grp * 4;
    ull*       wr1 = pB + hp1 * 34 + grp * 4;
    const ull* rd  = pB + ehp * 34 + eb;

    for (int t = 0; t < tmax; t++) {
        if (tid < 4) xi[tid] = x_in[orig[tid] * S + t];
        __syncthreads();    // (1) xi ready; hd from previous epilogue visible

        float2 pf = __ldg(reinterpret_cast<const float2*>(g_P + xi[eb] * H) + ehp);

        ull a0[4], a1[4];
#pragma unroll
        for (int b = 0; b < 4; b++) { a0[b] = 0ull; a1[b] = 0ull; }

        // 32 kp, 2-kp unrolled, double-buffered W prefetch
        ulonglong2 wa0 = __ldg(Wb + (kb + 0) * HPAIR + hp0);
        ulonglong2 wa1 = __ldg(Wb + (kb + 0) * HPAIR + hp1);
        ulonglong2 wc0 = __ldg(Wb + (kb + 1) * HPAIR + hp0);
        ulonglong2 wc1 = __ldg(Wb + (kb + 1) * HPAIR + hp1);
#pragma unroll 4
        for (int c = 0; c < 32; c += 2) {
            const int n0 = (c + 2) & 31;
            const int n1 = (c + 3) & 31;
            ulonglong2 wb0 = __ldg(Wb + (kb + n0) * HPAIR + hp0);
            ulonglong2 wb1 = __ldg(Wb + (kb + n0) * HPAIR + hp1);
            {
                const float4* hk =
                    reinterpret_cast<const float4*>(hd + (unsigned)(kb + c) * 4);
                float4 qA = hk[0];   // b0:(ke,ko), b1:(ke,ko)
                float4 qB = hk[1];   // b2:(ke,ko), b3:(ke,ko)
                {   // k even
                    ull d0 = pk2(qA.x, qA.x), d1 = pk2(qA.z, qA.z);
                    ull d2 = pk2(qB.x, qB.x), d3 = pk2(qB.z, qB.z);
                    fma2(a0[0], wa0.x, d0); fma2(a0[1], wa0.x, d1);
                    fma2(a0[2], wa0.x, d2); fma2(a0[3], wa0.x, d3);
                    fma2(a1[0], wa1.x, d0); fma2(a1[1], wa1.x, d1);
                    fma2(a1[2], wa1.x, d2); fma2(a1[3], wa1.x, d3);
                }
                {   // k odd
                    ull d0 = pk2(qA.y, qA.y), d1 = pk2(qA.w, qA.w);
                    ull d2 = pk2(qB.y, qB.y), d3 = pk2(qB.w, qB.w);
                    fma2(a0[0], wa0.y, d0); fma2(a0[1], wa0.y, d1);
                    fma2(a0[2], wa0.y, d2); fma2(a0[3], wa0.y, d3);
                    fma2(a1[0], wa1.y, d0); fma2(a1[1], wa1.y, d1);
                    fma2(a1[2], wa1.y, d2); fma2(a1[3], wa1.y, d3);
                }
            }
            ulonglong2 wd0 = __ldg(Wb + (kb + n1) * HPAIR + hp0);
            ulonglong2 wd1 = __ldg(Wb + (kb + n1) * HPAIR + hp1);
            {
                const float4* hk =
                    reinterpret_cast<const float4*>(hd + (unsigned)(kb + c + 1) * 4);
                float4 qA = hk[0];
                float4 qB = hk[1];
                {   // k even
                    ull d0 = pk2(qA.x, qA.x), d1 = pk2(qA.z, qA.z);
                    ull d2 = pk2(qB.x, qB.x), d3 = pk2(qB.z, qB.z);
                    fma2(a0[0], wc0.x, d0); fma2(a0[1], wc0.x, d1);
                    fma2(a0[2], wc0.x, d2); fma2(a0[3], wc0.x, d3);
                    fma2(a1[0], wc1.x, d0); fma2(a1[1], wc1.x, d1);
                    fma2(a1[2], wc1.x, d2); fma2(a1[3], wc1.x, d3);
                }
                {   // k odd
                    ull d0 = pk2(qA.y, qA.y), d1 = pk2(qA.w, qA.w);
                    ull d2 = pk2(qB.y, qB.y), d3 = pk2(qB.w, qB.w);
                    fma2(a0[0], wc0.y, d0); fma2(a0[1], wc0.y, d1);
                    fma2(a0[2], wc0.y, d2); fma2(a0[3], wc0.y, d3);
                    fma2(a1[0], wc1.y, d0); fma2(a1[1], wc1.y, d1);
                    fma2(a1[2], wc1.y, d2); fma2(a1[3], wc1.y, d3);
                }
            }
            wa0 = wb0; wa1 = wb1; wc0 = wd0; wc1 = wd1;
        }

        // write partials: pB[hp][grp][b]
        *reinterpret_cast<ulonglong2*>(wr0)     = make_ulonglong2(a0[0], a0[1]);
        *reinterpret_cast<ulonglong2*>(wr0 + 2) = make_ulonglong2(a0[2], a0[3]);
        *reinterpret_cast<ulonglong2*>(wr1)     = make_ulonglong2(a1[0], a1[1]);
        *reinterpret_cast<ulonglong2*>(wr1 + 2) = make_ulonglong2(a1[2], a1[3]);
        __syncthreads();    // (2) partials visible; all hd reads complete

        // distributed epilogue: (h-pair ehp, batch eb)
        ull s = rd[0];
#pragma unroll
        for (int g = 1; g < 8; g++) {
            ull v = rd[g * 4];
            add2(s, s, v);
        }
        add2(s, s, pk2(pf.x, pf.y));

        float x0, x1;
        upk2(s, x0, x1);
        const float v0 = tanhf(x0);
        const float v1 = tanhf(x1);

        // non-duplicated state write: one STS.64 per thread
        hd[ehp * 4 + eb] = pk2(v0, v1);

        if (t == slen[eb] - 1)
            *reinterpret_cast<float2*>(g_last + orig[eb] * H + 2 * ehp) =
                make_float2(v0, v1);
    }
}

// ---------------------------------------------------------------------------
// Kernel: bucketed persistent RNN.
//   bid 0..103   : NB=4, rows 608 + 4*bid (longest 416 rows)
//   bid 104..179 : NB=8, rows 600 - 8*(bid-104) (descending; shortest last)
// ---------------------------------------------------------------------------
__global__ void __launch_bounds__(THR, 1) rnn_kernel(const int* __restrict__ x_in) {
    extern __shared__ char smem[];
    const int bid = blockIdx.x;
    if (bid < N_CTA4) {
        rnn_body4(x_in, 608 + 4 * bid, smem);
    } else {
        rnn_body8(x_in, 600 - 8 * (bid - N_CTA4), smem);
    }
}

// ---------------------------------------------------------------------------
// Kernel: MLP head — one rnn-style NB=8 step (relu) + k-split logits.
// ---------------------------------------------------------------------------
__global__ void __launch_bounds__(THR, 1) mlp_kernel(const float* __restrict__ b1,
                                                     const float* __restrict__ b2,
                                                     float* __restrict__ out) {
    extern __shared__ char smem[];
    ull*   hT2  = reinterpret_cast<ull*>(smem + MLP_HT2);    // [512][4]
    ull*   pB   = reinterpret_cast<ull*>(smem + MLP_PB);     // [256][34]
    float* hlin = reinterpret_cast<float*>(smem + MLP_HLIN); // [8][512]
    float* red  = reinterpret_cast<float*>(smem + MLP_RED);  // [256][5]

    const int tid  = threadIdx.x;
    const int grp  = tid >> 8;
    const int hp   = tid & (HPAIR - 1);
    const int base = blockIdx.x * BT;

    const int eh   = tid >> 1;
    const int eq   = tid & 1;
    const int ehp  = eh >> 1;
    const int epar = eh & 1;

    hT2[eh * 4 + 2 * eq + 0] = pk2(g_last[(base + 4 * eq + 0) * H + eh],
                                   g_last[(base + 4 * eq + 1) * H + eh]);
    hT2[eh * 4 + 2 * eq + 1] = pk2(g_last[(base + 4 * eq + 2) * H + eh],
                                   g_last[(base + 4 * eq + 3) * H + eh]);
    __syncthreads();

    const ulonglong2* Wp =
        reinterpret_cast<const ulonglong2*>(g_W1p) + (grp * 64) * HPAIR + hp;

    ull a0[4], a1[4];
#pragma unroll
    for (int p = 0; p < 4; p++) { a0[p] = 0ull; a1[p] = 0ull; }

    gemm_g6<8>(Wp, hT2, grp * 128, a0, a1);

    ull* myPB = pB + hp * 34 + grp * 8;
#pragma unroll
    for (int p = 0; p < 4; p += 2)
        *reinterpret_cast<ulonglong2*>(myPB + p) = make_ulonglong2(a0[p], a0[p + 1]);
#pragma unroll
    for (int p = 0; p < 4; p += 2)
        *reinterpret_cast<ulonglong2*>(myPB + 4 + p) = make_ulonglong2(a1[p], a1[p + 1]);
    __syncthreads();

    {
        const ull* ePB = pB + ehp * 34 + epar * 4 + eq * 2;
        ull s[2];
#pragma unroll
        for (int q = 0; q < 2; q++) s[q] = ePB[q];
#pragma unroll
        for (int g = 1; g < 4; g++) {
#pragma unroll
            for (int q = 0; q < 2; q++) {
                ull v = ePB[g * 8 + q];
                add2(s[q], s[q], v);
            }
        }
        const float bv = __ldg(b1 + eh);
#pragma unroll
        for (int q = 0; q < 2; q++) {
            float x, y;
            upk2(s[q], x, y);
            hlin[(eq * 4 + 2 * q + 0) * H + eh] = fmaxf(x + bv, 0.f);
            hlin[(eq * 4 + 2 * q + 1) * H + eh] = fmaxf(y + bv, 0.f);
        }
    }
    __syncthreads();

    {
        const int kq = tid >> 8;
        const int r  = tid & 255;
        const int b  = r >> 5;
        const int c  = r & 31;
        float acc = 0.f;
        const float* hb = hlin + b * H + kq * 128;
        const float* w2 = g_W2T + (kq * 128) * C + c;
#pragma unroll 8
        for (int k = 0; k < 128; k++) acc += hb[k] * __ldg(w2 + k * C);
        red[r * 5 + kq] = acc;
    }
    __syncthreads();

    if (tid < 256) {
        const int b = tid >> 5, c = tid & 31;
        float acc = __ldg(b2 + c) + red[tid * 5 + 0] + red[tid * 5 + 1]
                  + red[tid * 5 + 2] + red[tid * 5 + 3];
        out[(base + b) * C + c] = acc;
    }
}

// ---------------------------------------------------------------------------
extern "C" void kernel_launch(void* const* d_in, const int* in_sizes, int n_in,
                              void* d_out, int out_size) {
    const int*   x_in   = (const int*)  d_in[0];
    const int*   x_lens = (const int*)  d_in[1];
    const float* emb    = (const float*)d_in[2];
    const float* W_ih   = (const float*)d_in[3];
    const float* b_ih   = (const float*)d_in[4];
    const float* W_hh   = (const float*)d_in[5];
    const float* b_hh   = (const float*)d_in[6];
    const float* W1w    = (const float*)d_in[7];
    const float* b1     = (const float*)d_in[8];
    const float* W2w    = (const float*)d_in[9];
    const float* b2     = (const float*)d_in[10];
    float* out = (float*)d_out;

    cudaFuncSetAttribute(rnn_kernel,
                         cudaFuncAttributeMaxDynamicSharedMemorySize, RNN_SMEM);
    cudaFuncSetAttribute(mlp_kernel,
                         cudaFuncAttributeMaxDynamicSharedMemorySize, MLP_SMEM);

    setup_kernel<<<SETUP_GRID, 256>>>(x_lens, emb, W_ih, b_ih, b_hh,
                                      W_hh, W1w, W2w);
    rnn_kernel<<<RNN_GRID, THR, RNN_SMEM>>>(x_in);
    mlp_kernel<<<B / BT, THR, MLP_SMEM>>>(b1, b2, out);
}